// round 14
// baseline (speedup 1.0000x reference)
#include <cuda_runtime.h>
#include <cuda_bf16.h>
#include <cuda_fp16.h>
#include <cstdint>

#define NN 50000
#define NE 800000
#define D  256
#define NB ((NN + 1023) / 1024)

// ---------------- scratch (static device memory, no allocs) ----------------
__device__ float g_bufA[NN * D];
__device__ float g_bufB[NN * D];
__device__ __half g_projh[NN * D];
__device__ float g_skip[NN * D];
__device__ float g_ssrc[NN * 16];
__device__ float g_stgt[NN * 16];
__device__ float g_c   [48];
__device__ __nv_bfloat16 g_Ahi[NN * D];
__device__ __nv_bfloat16 g_Alo[NN * D];
__device__ __nv_bfloat16 g_Bhi[5 * D * D];
__device__ __nv_bfloat16 g_Blo[5 * D * D];
// CSR
__device__ int   g_cnt[NN];
__device__ int   g_rowptr[NN + 1];
__device__ int   g_pos[NN];
__device__ int   g_partial[NN];
__device__ int   g_bsum[64];
__device__ int2  g_epack[NE];

// ---------------- helpers ----------------------------------------------------
__device__ __forceinline__ uint32_t smem_u32(const void* p) {
    uint32_t a;
    asm("{ .reg .u64 t; cvta.to.shared.u64 t, %1; cvt.u32.u64 %0, t; }" : "=r"(a) : "l"(p));
    return a;
}
__device__ __forceinline__ void ldmx4(uint32_t& r0, uint32_t& r1, uint32_t& r2, uint32_t& r3,
                                      uint32_t addr) {
    asm volatile("ldmatrix.sync.aligned.m8n8.x4.shared.b16 {%0,%1,%2,%3}, [%4];"
                 : "=r"(r0), "=r"(r1), "=r"(r2), "=r"(r3) : "r"(addr));
}
__device__ __forceinline__ void mma_bf16(float* d, const uint32_t* a, const uint32_t* b) {
    asm volatile(
        "mma.sync.aligned.m16n8k16.row.col.f32.bf16.bf16.f32 "
        "{%0,%1,%2,%3}, {%4,%5,%6,%7}, {%8,%9}, {%0,%1,%2,%3};"
        : "+f"(d[0]), "+f"(d[1]), "+f"(d[2]), "+f"(d[3])
        : "r"(a[0]), "r"(a[1]), "r"(a[2]), "r"(a[3]), "r"(b[0]), "r"(b[1]));
}
__device__ __forceinline__ void cp_async16(uint32_t sdst, const void* gsrc) {
    asm volatile("cp.async.cg.shared.global [%0], [%1], 16;" :: "r"(sdst), "l"(gsrc) : "memory");
}
__device__ __forceinline__ void cp_commit() {
    asm volatile("cp.async.commit_group;" ::: "memory");
}
template <int N>
__device__ __forceinline__ void cp_wait() {
    asm volatile("cp.async.wait_group %0;" :: "n"(N) : "memory");
}
#define SWZ64(x) ((x) ^ (((x) >> 3) & 0x30))

// ---------------- fp32 -> split-bf16 conversion ------------------------------
__global__ void convA_kernel(const float* __restrict__ X, __nv_bfloat16* __restrict__ Ahi,
                             __nv_bfloat16* __restrict__ Alo, int total2) {
    int i = blockIdx.x * blockDim.x + threadIdx.x;
    if (i >= total2) return;
    float2 v = ((const float2*)X)[i];
    __nv_bfloat16 h0 = __float2bfloat16(v.x);
    __nv_bfloat16 h1 = __float2bfloat16(v.y);
    ((__nv_bfloat162*)Ahi)[i] = __halves2bfloat162(h0, h1);
    __nv_bfloat16 l0 = __float2bfloat16(v.x - __bfloat162float(h0));
    __nv_bfloat16 l1 = __float2bfloat16(v.y - __bfloat162float(h1));
    ((__nv_bfloat162*)Alo)[i] = __halves2bfloat162(l0, l1);
}

// all 5 weight sets in one launch.
__global__ void convB_all_kernel(const float* __restrict__ W0, const float* __restrict__ Ws0,
                                 const float* __restrict__ W1, const float* __restrict__ Ws1,
                                 const float* __restrict__ W2,
                                 __nv_bfloat16* __restrict__ Bhi, __nv_bfloat16* __restrict__ Blo) {
    int idx = blockIdx.x * blockDim.x + threadIdx.x;
    const int S128 = 256 * 128;
    const int S256 = 256 * 256;
    const float* W;
    int K, slot, loc;
    if (idx < 2 * S128) {
        slot = idx / S128; loc = idx % S128; K = 128;
        W = slot ? Ws0 : W0;
    } else {
        int r = idx - 2 * S128;
        if (r >= 3 * S256) return;
        slot = 2 + r / S256; loc = r % S256; K = 256;
        W = (slot == 2) ? W1 : (slot == 3) ? Ws1 : W2;
    }
    int k = loc / 256, n = loc & 255;
    float v = W[k * 256 + n];
    __nv_bfloat16 h = __float2bfloat16(v);
    size_t off = (size_t)slot * D * D + (size_t)n * K + k;
    Bhi[off] = h;
    Blo[off] = __float2bfloat16(v - __bfloat162float(h));
}

// ---------------- zero the score accumulators --------------------------------
__global__ void zero_scores_kernel(float* __restrict__ ssrc, float* __restrict__ stgt, int total) {
    int i = blockIdx.x * blockDim.x + threadIdx.x;
    if (i < total) { ssrc[i] = 0.f; stgt[i] = 0.f; }
}

// ---------------- cp.async double-buffered mma.sync GEMM --------------------
// blockIdx.z==0: proj weights -> fp16 H + fused attention scores (atomicAdd).
// blockIdx.z==1: skip weights -> fp32 Cskip.
#define ST_AHI 0
#define ST_ALO 8192
#define ST_BHI 16384
#define ST_BLO 24576
#define ST_STRIDE 32768
#define GEMM_SMEM 65536

__global__ __launch_bounds__(256, 1) void gemm_mma_kernel(
    const __nv_bfloat16* __restrict__ Ahi, const __nv_bfloat16* __restrict__ Alo,
    const __nv_bfloat16* __restrict__ Bhi0, const __nv_bfloat16* __restrict__ Blo0,
    float* __restrict__ Cskip, __half* __restrict__ H,
    const float* __restrict__ avs, const float* __restrict__ avt,
    float* __restrict__ ssrc, float* __restrict__ stgt,
    int M, int K, int nh) {
    extern __shared__ char smem[];
    int tid = threadIdx.x, wid = tid >> 5, lane = tid & 31;
    int m0 = blockIdx.y * 128, n0 = blockIdx.x * 128;
    int z = blockIdx.z;
    int wm = wid >> 2, wn = wid & 3;
    const __nv_bfloat16* Bhi = Bhi0 + (size_t)z * D * D;
    const __nv_bfloat16* Blo = Blo0 + (size_t)z * D * D;

    uint32_t sb = smem_u32(smem);
    float acc[4][4][4];
#pragma unroll
    for (int i = 0; i < 4; i++)
#pragma unroll
        for (int j = 0; j < 4; j++)
#pragma unroll
            for (int q = 0; q < 4; q++) acc[i][j][q] = 0.f;

    int iters = K >> 5;
    auto issue_load = [&](int c) {
        uint32_t st = sb + (c & 1) * ST_STRIDE;
#pragma unroll
        for (int it = 0; it < 2; it++) {
            int i = tid + it * 256;
            int row = i >> 2, c16 = i & 3;
            uint32_t soff = SWZ64(row * 64 + c16 * 16);
            int gm = m0 + row;
            if (gm >= M) gm = M - 1;
            size_t go = (size_t)gm * K + c * 32 + c16 * 8;
            cp_async16(st + ST_AHI + soff, Ahi + go);
            cp_async16(st + ST_ALO + soff, Alo + go);
            size_t gb = (size_t)(n0 + row) * K + c * 32 + c16 * 8;
            cp_async16(st + ST_BHI + soff, Bhi + gb);
            cp_async16(st + ST_BLO + soff, Blo + gb);
        }
        cp_commit();
    };
    issue_load(0);
    for (int c = 0; c < iters; c++) {
        if (c + 1 < iters) { issue_load(c + 1); cp_wait<1>(); }
        else cp_wait<0>();
        __syncthreads();
        uint32_t st = sb + (c & 1) * ST_STRIDE;
        uint32_t sA0 = st + ST_AHI, sA1 = st + ST_ALO;
        uint32_t sB0 = st + ST_BHI, sB1 = st + ST_BLO;
#pragma unroll
        for (int ks = 0; ks < 2; ks++) {
            uint32_t ah[4][4], al[4][4], bh[4][2], bl[4][2];
#pragma unroll
            for (int mf = 0; mf < 4; mf++) {
                int row = wm * 64 + mf * 16 + (lane & 15);
                uint32_t off = SWZ64(row * 64 + ks * 32 + (lane >> 4) * 16);
                ldmx4(ah[mf][0], ah[mf][1], ah[mf][2], ah[mf][3], sA0 + off);
                ldmx4(al[mf][0], al[mf][1], al[mf][2], al[mf][3], sA1 + off);
            }
#pragma unroll
            for (int nf2 = 0; nf2 < 2; nf2++) {
                int row = wn * 32 + nf2 * 16 + (lane & 15);
                uint32_t off = SWZ64(row * 64 + ks * 32 + (lane >> 4) * 16);
                uint32_t t0, t1, t2, t3;
                ldmx4(t0, t1, t2, t3, sB0 + off);
                bh[nf2 * 2][0] = t0; bh[nf2 * 2][1] = t2;
                bh[nf2 * 2 + 1][0] = t1; bh[nf2 * 2 + 1][1] = t3;
                ldmx4(t0, t1, t2, t3, sB1 + off);
                bl[nf2 * 2][0] = t0; bl[nf2 * 2][1] = t2;
                bl[nf2 * 2 + 1][0] = t1; bl[nf2 * 2 + 1][1] = t3;
            }
#pragma unroll
            for (int mf = 0; mf < 4; mf++)
#pragma unroll
                for (int nf = 0; nf < 4; nf++) {
                    mma_bf16(acc[mf][nf], ah[mf], bh[nf]);
                    mma_bf16(acc[mf][nf], ah[mf], bl[nf]);
                    mma_bf16(acc[mf][nf], al[mf], bh[nf]);
                }
        }
        __syncthreads();
    }

    if (z == 0) {
        // ---- writeback fp16 proj + fused attention scores ----
        int colbase = n0 + wn * 32 + (lane & 3) * 2;
#pragma unroll
        for (int mf = 0; mf < 4; mf++) {
            int r0 = m0 + wm * 64 + mf * 16 + (lane >> 2);
#pragma unroll
            for (int nf = 0; nf < 4; nf++) {
                int col = colbase + nf * 8;
                if (r0 < M)
                    *(__half2*)(H + (size_t)r0 * 256 + col) =
                        __float22half2_rn(make_float2(acc[mf][nf][0], acc[mf][nf][1]));
                if (r0 + 8 < M)
                    *(__half2*)(H + (size_t)(r0 + 8) * 256 + col) =
                        __float22half2_rn(make_float2(acc[mf][nf][2], acc[mf][nf][3]));
            }
            // fused scores: partials per (head-half, row)
            float ps[2][2] = {{0.f, 0.f}, {0.f, 0.f}};
            float pt[2][2] = {{0.f, 0.f}, {0.f, 0.f}};
#pragma unroll
            for (int nf = 0; nf < 4; nf++) {
                int col = colbase + nf * 8;
                float2 a1 = *(const float2*)(avs + col);
                float2 a2 = *(const float2*)(avt + col);
                int hh = (nh == 16) ? (nf >> 1) : 0;
                ps[hh][0] += acc[mf][nf][0] * a1.x + acc[mf][nf][1] * a1.y;
                ps[hh][1] += acc[mf][nf][2] * a1.x + acc[mf][nf][3] * a1.y;
                pt[hh][0] += acc[mf][nf][0] * a2.x + acc[mf][nf][1] * a2.y;
                pt[hh][1] += acc[mf][nf][2] * a2.x + acc[mf][nf][3] * a2.y;
            }
#pragma unroll
            for (int o = 1; o < 4; o <<= 1) {
#pragma unroll
                for (int hh = 0; hh < 2; hh++)
#pragma unroll
                    for (int rr = 0; rr < 2; rr++) {
                        ps[hh][rr] += __shfl_xor_sync(0xffffffffu, ps[hh][rr], o);
                        pt[hh][rr] += __shfl_xor_sync(0xffffffffu, pt[hh][rr], o);
                    }
            }
            if ((lane & 3) == 0) {
                if (nh == 16) {
                    int h0 = (n0 + wn * 32) >> 4;
                    if (r0 < M) {
                        atomicAdd(&ssrc[r0 * 16 + h0], ps[0][0]);
                        atomicAdd(&ssrc[r0 * 16 + h0 + 1], ps[1][0]);
                        atomicAdd(&stgt[r0 * 16 + h0], pt[0][0]);
                        atomicAdd(&stgt[r0 * 16 + h0 + 1], pt[1][0]);
                    }
                    if (r0 + 8 < M) {
                        atomicAdd(&ssrc[(r0 + 8) * 16 + h0], ps[0][1]);
                        atomicAdd(&ssrc[(r0 + 8) * 16 + h0 + 1], ps[1][1]);
                        atomicAdd(&stgt[(r0 + 8) * 16 + h0], pt[0][1]);
                        atomicAdd(&stgt[(r0 + 8) * 16 + h0 + 1], pt[1][1]);
                    }
                } else {
                    if (r0 < M) {
                        atomicAdd(&ssrc[r0], ps[0][0] + ps[1][0]);
                        atomicAdd(&stgt[r0], pt[0][0] + pt[1][0]);
                    }
                    if (r0 + 8 < M) {
                        atomicAdd(&ssrc[r0 + 8], ps[0][1] + ps[1][1]);
                        atomicAdd(&stgt[r0 + 8], pt[0][1] + pt[1][1]);
                    }
                }
            }
        }
    } else {
        // ---- writeback fp32 skip ----
#pragma unroll
        for (int mf = 0; mf < 4; mf++) {
            int r0 = m0 + wm * 64 + mf * 16 + (lane >> 2);
#pragma unroll
            for (int nf = 0; nf < 4; nf++) {
                int col = n0 + wn * 32 + nf * 8 + (lane & 3) * 2;
                if (r0 < M)
                    *(float2*)(Cskip + (size_t)r0 * 256 + col) =
                        make_float2(acc[mf][nf][0], acc[mf][nf][1]);
                if (r0 + 8 < M)
                    *(float2*)(Cskip + (size_t)(r0 + 8) * 256 + col) =
                        make_float2(acc[mf][nf][2], acc[mf][nf][3]);
            }
        }
    }
}

// ---------------- CSR build --------------------------------------------------
__global__ void csr_zero_kernel(int* __restrict__ cnt) {
    int i = blockIdx.x * blockDim.x + threadIdx.x;
    if (i < NN) cnt[i] = 0;
}
__global__ void csr_count_kernel(const int* __restrict__ tgt, int* __restrict__ cnt) {
    int e = blockIdx.x * blockDim.x + threadIdx.x;
    if (e < NE) atomicAdd(&cnt[tgt[e]], 1);
}
// multi-block scan, phase 1: per-block inclusive scan + block sums
__global__ void csr_scan1_kernel(const int* __restrict__ cnt, int* __restrict__ partial,
                                 int* __restrict__ bsum) {
    __shared__ int sh[1024];
    int b = blockIdx.x, tid = threadIdx.x;
    int i = b * 1024 + tid;
    int v = (i < NN) ? cnt[i] : 0;
    sh[tid] = v;
    __syncthreads();
    for (int off = 1; off < 1024; off <<= 1) {
        int t = (tid >= off) ? sh[tid - off] : 0;
        __syncthreads();
        sh[tid] += t;
        __syncthreads();
    }
    if (i < NN) partial[i] = sh[tid];
    if (tid == 1023) bsum[b] = sh[1023];
}
// phase 2: exclusive scan of block sums (NB <= 64, single tiny block)
__global__ void csr_scan2_kernel(int* __restrict__ bsum) {
    if (threadIdx.x == 0) {
        int run = 0;
        for (int j = 0; j < NB; j++) {
            int t = bsum[j];
            bsum[j] = run;
            run += t;
        }
    }
}
// phase 3: apply offsets -> rowptr, pos
__global__ void csr_scan3_kernel(const int* __restrict__ cnt, const int* __restrict__ partial,
                                 const int* __restrict__ bsum,
                                 int* __restrict__ rowptr, int* __restrict__ pos) {
    int i = blockIdx.x * blockDim.x + threadIdx.x;
    if (i >= NN) return;
    int inc = partial[i] + bsum[i >> 10];
    rowptr[i + 1] = inc;
    pos[i] = inc - cnt[i];
    if (i == 0) rowptr[0] = 0;
}
__global__ void csr_scatter_kernel(const int* __restrict__ src, const int* __restrict__ tgt,
                                   const float* __restrict__ prob, int* __restrict__ pos,
                                   int2* __restrict__ epack) {
    int e = blockIdx.x * blockDim.x + threadIdx.x;
    if (e >= NE) return;
    int i = atomicAdd(&pos[tgt[e]], 1);
    epack[i] = make_int2(src[e], __float_as_int(prob[e]));
}

// ---------------- tp constants for all 3 layers in one launch ---------------
__global__ void tp_const_all_kernel(const float* __restrict__ Wtp0, const float* __restrict__ a0,
                                    const float* __restrict__ Wtp1, const float* __restrict__ a1,
                                    const float* __restrict__ Wtp2, const float* __restrict__ a2,
                                    float* __restrict__ c) {
    __shared__ float tmp[D];
    int L = blockIdx.x;
    int j = threadIdx.x;
    const float* W = (L == 0) ? Wtp0 : (L == 1) ? Wtp1 : Wtp2;
    const float* A = (L == 0) ? a0 : (L == 1) ? a1 : a2;
    tmp[j] = W[j] * A[j];
    __syncthreads();
    if (L < 2) {
        if (j < 16) {
            float s = 0.f;
            for (int f = 0; f < 16; f++) s += tmp[j * 16 + f];
            c[L * 16 + j] = s;
        }
    } else {
        if (j == 0) {
            float s = 0.f;
            for (int f = 0; f < 256; f++) s += tmp[f];
            c[32] = s;
        }
    }
}

// ---------------- fused node aggregation + epilogue -------------------------
// TWO warps per target node (edge range split), 4-wide edge unroll per warp.
// Partial acc/den combined through smem; even warp runs the epilogue.
template <int NH, bool LN, bool WBF, bool WOUT>
__global__ __launch_bounds__(256) void node_aggr_kernel(
    const int* __restrict__ rowptr, const int2* __restrict__ epack,
    const float* __restrict__ ssrc, const float* __restrict__ stgt,
    const float* __restrict__ c,
    const __half* __restrict__ projh, const float* __restrict__ skip,
    const float* __restrict__ bias,
    const float* __restrict__ lng, const float* __restrict__ lnb,
    float* __restrict__ out, __nv_bfloat16* __restrict__ ohi,
    __nv_bfloat16* __restrict__ olo) {
    __shared__ float sacc[4][256];
    __shared__ float sden[4][16];
    int tid = threadIdx.x;
    int lane = tid & 31;
    int pl = tid >> 6;            // pair index within block, 0..3
    int half = (tid >> 5) & 1;    // which warp of the pair
    int n = blockIdx.x * 4 + pl;
    bool active = (n < NN);
    int myhead = (NH == 16) ? (lane >> 1) : 0;

    float stg = 0.f, cc = 0.f;
    int beg = 0, end = 0;
    if (active) {
        if (lane < NH) {
            stg = stgt[n * NH + lane];
            cc  = c[lane];
        }
        beg = rowptr[n];
        end = rowptr[n + 1];
        int mid = beg + ((end - beg + 1) >> 1);
        if (half) beg = mid; else end = mid;
    }

    float acc[8];
#pragma unroll
    for (int q = 0; q < 8; q++) acc[q] = 0.f;
    float den = 0.f;

    int i = beg;
    for (; i + 4 <= end; i += 4) {
        int2 e0 = epack[i], e1 = epack[i + 1], e2 = epack[i + 2], e3 = epack[i + 3];
        uint4 pv0 = ((const uint4*)(projh + (size_t)e0.x * D))[lane];
        uint4 pv1 = ((const uint4*)(projh + (size_t)e1.x * D))[lane];
        uint4 pv2 = ((const uint4*)(projh + (size_t)e2.x * D))[lane];
        uint4 pv3 = ((const uint4*)(projh + (size_t)e3.x * D))[lane];
        float w0 = 0.f, w1 = 0.f, w2 = 0.f, w3 = 0.f;
        if (lane < NH) {
            float v0 = ssrc[e0.x * NH + lane] + stg + __int_as_float(e0.y) * cc;
            float v1 = ssrc[e1.x * NH + lane] + stg + __int_as_float(e1.y) * cc;
            float v2 = ssrc[e2.x * NH + lane] + stg + __int_as_float(e2.y) * cc;
            float v3 = ssrc[e3.x * NH + lane] + stg + __int_as_float(e3.y) * cc;
            v0 = v0 > 0.f ? v0 : 0.2f * v0;
            v1 = v1 > 0.f ? v1 : 0.2f * v1;
            v2 = v2 > 0.f ? v2 : 0.2f * v2;
            v3 = v3 > 0.f ? v3 : 0.2f * v3;
            w0 = __expf(v0); w1 = __expf(v1); w2 = __expf(v2); w3 = __expf(v3);
            den += (w0 + w1) + (w2 + w3);
        }
        float wj0 = __shfl_sync(0xffffffffu, w0, myhead);
        float wj1 = __shfl_sync(0xffffffffu, w1, myhead);
        float wj2 = __shfl_sync(0xffffffffu, w2, myhead);
        float wj3 = __shfl_sync(0xffffffffu, w3, myhead);
        const __half2* h0 = (const __half2*)&pv0;
        const __half2* h1 = (const __half2*)&pv1;
        const __half2* h2 = (const __half2*)&pv2;
        const __half2* h3 = (const __half2*)&pv3;
#pragma unroll
        for (int q = 0; q < 4; q++) {
            float2 f0 = __half22float2(h0[q]);
            float2 f1 = __half22float2(h1[q]);
            float2 f2 = __half22float2(h2[q]);
            float2 f3 = __half22float2(h3[q]);
            acc[q * 2 + 0] += (wj0 * f0.x + wj1 * f1.x) + (wj2 * f2.x + wj3 * f3.x);
            acc[q * 2 + 1] += (wj0 * f0.y + wj1 * f1.y) + (wj2 * f2.y + wj3 * f3.y);
        }
    }
    for (; i < end; i++) {
        int2 e0 = epack[i];
        uint4 pv0 = ((const uint4*)(projh + (size_t)e0.x * D))[lane];
        float w0 = 0.f;
        if (lane < NH) {
            float v0 = ssrc[e0.x * NH + lane] + stg + __int_as_float(e0.y) * cc;
            v0 = v0 > 0.f ? v0 : 0.2f * v0;
            w0 = __expf(v0);
            den += w0;
        }
        float wj0 = __shfl_sync(0xffffffffu, w0, myhead);
        const __half2* h0 = (const __half2*)&pv0;
#pragma unroll
        for (int q = 0; q < 4; q++) {
            float2 f0 = __half22float2(h0[q]);
            acc[q * 2 + 0] += wj0 * f0.x;
            acc[q * 2 + 1] += wj0 * f0.y;
        }
    }

    // combine the pair: odd warp dumps partials to smem, even warp adds them
    if (active && half) {
#pragma unroll
        for (int k = 0; k < 2; k++)
            ((float4*)sacc[pl])[lane * 2 + k] =
                make_float4(acc[k * 4], acc[k * 4 + 1], acc[k * 4 + 2], acc[k * 4 + 3]);
        if (lane < NH) sden[pl][lane] = den;
    }
    __syncthreads();
    if (!active || half) return;
#pragma unroll
    for (int k = 0; k < 2; k++) {
        float4 s = ((const float4*)sacc[pl])[lane * 2 + k];
        acc[k * 4 + 0] += s.x;
        acc[k * 4 + 1] += s.y;
        acc[k * 4 + 2] += s.z;
        acc[k * 4 + 3] += s.w;
    }
    if (lane < NH) den += sden[pl][lane];

    // epilogue: cols 8*lane + 0..7
    float vals[8];
    size_t base = (size_t)n * D;
    float dh = __shfl_sync(0xffffffffu, den, myhead) + 1e-16f;
    float rdh = 1.f / dh;
#pragma unroll
    for (int k = 0; k < 2; k++) {
        float4 sk = ((const float4*)(skip + base))[lane * 2 + k];
        float4 bi = ((const float4*)bias)[lane * 2 + k];
        float4 r;
        r.x = acc[k * 4 + 0] * rdh + sk.x + bi.x;
        r.y = acc[k * 4 + 1] * rdh + sk.y + bi.y;
        r.z = acc[k * 4 + 2] * rdh + sk.z + bi.z;
        r.w = acc[k * 4 + 3] * rdh + sk.w + bi.w;
        vals[k * 4 + 0] = r.x > 0.f ? r.x : (__expf(r.x) - 1.f);
        vals[k * 4 + 1] = r.y > 0.f ? r.y : (__expf(r.y) - 1.f);
        vals[k * 4 + 2] = r.z > 0.f ? r.z : (__expf(r.z) - 1.f);
        vals[k * 4 + 3] = r.w > 0.f ? r.w : (__expf(r.w) - 1.f);
    }
    if (LN) {
        float s = 0.f;
#pragma unroll
        for (int q = 0; q < 8; q++) s += vals[q];
#pragma unroll
        for (int o = 16; o > 0; o >>= 1) s += __shfl_xor_sync(0xffffffffu, s, o);
        float mean = s * (1.f / 256.f);
        float v2 = 0.f;
#pragma unroll
        for (int q = 0; q < 8; q++) {
            vals[q] -= mean;
            v2 += vals[q] * vals[q];
        }
#pragma unroll
        for (int o = 16; o > 0; o >>= 1) v2 += __shfl_xor_sync(0xffffffffu, v2, o);
        float rstd = rsqrtf(v2 * (1.f / 256.f) + 1e-5f);
#pragma unroll
        for (int k = 0; k < 2; k++) {
            float4 gg = ((const float4*)lng)[lane * 2 + k];
            float4 bb = ((const float4*)lnb)[lane * 2 + k];
            vals[k * 4 + 0] = vals[k * 4 + 0] * rstd * gg.x + bb.x;
            vals[k * 4 + 1] = vals[k * 4 + 1] * rstd * gg.y + bb.y;
            vals[k * 4 + 2] = vals[k * 4 + 2] * rstd * gg.z + bb.z;
            vals[k * 4 + 3] = vals[k * 4 + 3] * rstd * gg.w + bb.w;
        }
    }
#pragma unroll
    for (int k = 0; k < 2; k++) {
        float4 r = make_float4(vals[k * 4], vals[k * 4 + 1], vals[k * 4 + 2], vals[k * 4 + 3]);
        if (WOUT) ((float4*)(out + base))[lane * 2 + k] = r;
        if (WBF) {
            __nv_bfloat16 h0 = __float2bfloat16(r.x);
            __nv_bfloat16 h1 = __float2bfloat16(r.y);
            __nv_bfloat16 h2 = __float2bfloat16(r.z);
            __nv_bfloat16 h3 = __float2bfloat16(r.w);
            ((__nv_bfloat162*)(ohi + base))[lane * 4 + k * 2]     = __halves2bfloat162(h0, h1);
            ((__nv_bfloat162*)(ohi + base))[lane * 4 + k * 2 + 1] = __halves2bfloat162(h2, h3);
            ((__nv_bfloat162*)(olo + base))[lane * 4 + k * 2] = __halves2bfloat162(
                __float2bfloat16(r.x - __bfloat162float(h0)),
                __float2bfloat16(r.y - __bfloat162float(h1)));
            ((__nv_bfloat162*)(olo + base))[lane * 4 + k * 2 + 1] = __halves2bfloat162(
                __float2bfloat16(r.z - __bfloat162float(h2)),
                __float2bfloat16(r.w - __bfloat162float(h3)));
        }
    }
}

// ---------------- final gather ----------------------------------------------
__global__ void gather_kernel(const float* __restrict__ h, const int* __restrict__ x,
                              float4* __restrict__ out, int total4) {
    int idx = blockIdx.x * blockDim.x + threadIdx.x;
    if (idx >= total4) return;
    int i = idx / (D / 4), j = idx % (D / 4);
    out[idx] = ((const float4*)(h + (size_t)x[i] * D))[j];
}

// ---------------- host orchestration ----------------------------------------
static float* symaddr(const void* sym) {
    void* p = nullptr;
    cudaGetSymbolAddress(&p, sym);
    return (float*)p;
}
static __nv_bfloat16* symaddr_bf(const void* sym) {
    void* p = nullptr;
    cudaGetSymbolAddress(&p, sym);
    return (__nv_bfloat16*)p;
}
static __half* symaddr_h(const void* sym) {
    void* p = nullptr;
    cudaGetSymbolAddress(&p, sym);
    return (__half*)p;
}
static int* symaddr_i(const void* sym) {
    void* p = nullptr;
    cudaGetSymbolAddress(&p, sym);
    return (int*)p;
}

extern "C" void kernel_launch(void* const* d_in, const int* in_sizes, int n_in,
                              void* d_out, int out_size) {
    const float* nf   = (const float*)d_in[0];
    const int*   ei   = (const int*)  d_in[1];
    const float* prob = (const float*)d_in[2];
    const int*   x    = (const int*)  d_in[3];
    const float* W0     = (const float*)d_in[4];
    const float* a_src0 = (const float*)d_in[5];
    const float* a_tgt0 = (const float*)d_in[6];
    const float* Wtp0   = (const float*)d_in[7];
    const float* a_tp0  = (const float*)d_in[8];
    const float* Wskip0 = (const float*)d_in[9];
    const float* b0     = (const float*)d_in[10];
    const float* W1     = (const float*)d_in[11];
    const float* a_src1 = (const float*)d_in[12];
    const float* a_tgt1 = (const float*)d_in[13];
    const float* Wtp1   = (const float*)d_in[14];
    const float* a_tp1  = (const float*)d_in[15];
    const float* Wskip1 = (const float*)d_in[16];
    const float* b1     = (const float*)d_in[17];
    const float* ln1_g  = (const float*)d_in[18];
    const float* ln1_b  = (const float*)d_in[19];
    const float* W2     = (const float*)d_in[20];
    const float* a_src2 = (const float*)d_in[21];
    const float* a_tgt2 = (const float*)d_in[22];
    const float* Wtp2   = (const float*)d_in[23];
    const float* a_tp2  = (const float*)d_in[24];
    const float* b2     = (const float*)d_in[25];
    const float* ln2_g  = (const float*)d_in[26];
    const float* ln2_b  = (const float*)d_in[27];

    static cudaStream_t sCsr = nullptr;
    static cudaEvent_t evFork = nullptr, evJoin = nullptr;
    if (!sCsr) {
        cudaFuncSetAttribute(gemm_mma_kernel, cudaFuncAttributeMaxDynamicSharedMemorySize, GEMM_SMEM);
        cudaStreamCreateWithFlags(&sCsr, cudaStreamNonBlocking);
        cudaEventCreateWithFlags(&evFork, cudaEventDisableTiming);
        cudaEventCreateWithFlags(&evJoin, cudaEventDisableTiming);
    }

    const int* src = ei;
    const int* tgt = ei + NE;
    float* bufA = symaddr(g_bufA);
    float* bufB = symaddr(g_bufB);
    __half* projh = symaddr_h(g_projh);
    float* skip = symaddr(g_skip);
    float* ssrc = symaddr(g_ssrc);
    float* stgt = symaddr(g_stgt);
    float* cbuf = symaddr(g_c);
    __nv_bfloat16* Ahi = symaddr_bf(g_Ahi);
    __nv_bfloat16* Alo = symaddr_bf(g_Alo);
    __nv_bfloat16* Bhi = symaddr_bf(g_Bhi);
    __nv_bfloat16* Blo = symaddr_bf(g_Blo);
    int* cnt     = symaddr_i(g_cnt);
    int* rowptr  = symaddr_i(g_rowptr);
    int* pos     = symaddr_i(g_pos);
    int* partial = symaddr_i(g_partial);
    int* bsum    = symaddr_i(g_bsum);
    int2* epack  = (int2*)symaddr_i(g_epack);

    const size_t WS = (size_t)D * D;

    // ---- fork: CSR build on side stream (fast multi-block scan) ----
    cudaEventRecord(evFork, 0);
    cudaStreamWaitEvent(sCsr, evFork, 0);
    csr_zero_kernel<<<(NN + 255) / 256, 256, 0, sCsr>>>(cnt);
    csr_count_kernel<<<(NE + 255) / 256, 256, 0, sCsr>>>(tgt, cnt);
    csr_scan1_kernel<<<NB, 1024, 0, sCsr>>>(cnt, partial, bsum);
    csr_scan2_kernel<<<1, 32, 0, sCsr>>>(bsum);
    csr_scan3_kernel<<<(NN + 255) / 256, 256, 0, sCsr>>>(cnt, partial, bsum, rowptr, pos);
    csr_scatter_kernel<<<(NE + 255) / 256, 256, 0, sCsr>>>(src, tgt, prob, pos, epack);
    cudaEventRecord(evJoin, sCsr);

    // ---- main stream: conversions ----
    const int CONVB_TOTAL = 2 * 256 * 128 + 3 * 256 * 256;
    convB_all_kernel<<<(CONVB_TOTAL + 255) / 256, 256>>>(W0, Wskip0, W1, Wskip1, W2, Bhi, Blo);
    tp_const_all_kernel<<<3, 256>>>(Wtp0, a_tp0, Wtp1, a_tp1, Wtp2, a_tp2, cbuf);
    convA_kernel<<<(NN * 128 / 2 + 255) / 256, 256>>>(nf, Ahi, Alo, NN * 128 / 2);

    int aggGrid = (NN + 3) / 4;   // 2 warps per node, 4 nodes per 256-thread CTA
    dim3 ggrid2(2, (NN + 127) / 128, 2);
    dim3 ggrid1(2, (NN + 127) / 128, 1);
    int zsGrid = (NN * 16 + 255) / 256;

    // ---- layer 0: 128 -> 256, 16 heads, no LN ----
    zero_scores_kernel<<<zsGrid, 256>>>(ssrc, stgt, NN * 16);
    gemm_mma_kernel<<<ggrid2, 256, GEMM_SMEM>>>(Ahi, Alo, Bhi, Blo, skip, projh,
                                                a_src0, a_tgt0, ssrc, stgt, NN, 128, 16);
    cudaStreamWaitEvent(0, evJoin, 0);
    node_aggr_kernel<16, false, true, false><<<aggGrid, 256>>>(
        rowptr, epack, ssrc, stgt, cbuf, projh, skip, b0,
        nullptr, nullptr, nullptr, Ahi, Alo);

    // ---- layer 1: 256 -> 256, 16 heads, LN ----
    zero_scores_kernel<<<zsGrid, 256>>>(ssrc, stgt, NN * 16);
    gemm_mma_kernel<<<ggrid2, 256, GEMM_SMEM>>>(Ahi, Alo, Bhi + 2 * WS, Blo + 2 * WS, skip, projh,
                                                a_src1, a_tgt1, ssrc, stgt, NN, 256, 16);
    node_aggr_kernel<16, true, true, true><<<aggGrid, 256>>>(
        rowptr, epack, ssrc, stgt, cbuf + 16, projh, skip, b1,
        ln1_g, ln1_b, bufB, Ahi, Alo);

    // ---- layer 2: 256 -> 256, 1 head, identity skip, LN ----
    zero_scores_kernel<<<(NN + 255) / 256, 256>>>(ssrc, stgt, NN);
    gemm_mma_kernel<<<ggrid1, 256, GEMM_SMEM>>>(Ahi, Alo, Bhi + 4 * WS, Blo + 4 * WS, nullptr, projh,
                                                a_src2, a_tgt2, ssrc, stgt, NN, 256, 1);
    node_aggr_kernel<1, true, false, true><<<aggGrid, 256>>>(
        rowptr, epack, ssrc, stgt, cbuf + 32, projh, bufB, b2,
        ln2_g, ln2_b, bufA, nullptr, nullptr);

    gather_kernel<<<(out_size / 4 + 255) / 256, 256>>>(bufA, x, (float4*)d_out, out_size / 4);
}

// round 15
// speedup vs baseline: 1.1613x; 1.1613x over previous
#include <cuda_runtime.h>
#include <cuda_bf16.h>
#include <cuda_fp16.h>
#include <cstdint>

#define NN 50000
#define NE 800000
#define D  256
#define NB ((NN + 1023) / 1024)

// ---------------- scratch (static device memory, no allocs) ----------------
__device__ float g_bufA[NN * D];
__device__ float g_bufB[NN * D];
__device__ __half g_projh[NN * D];
__device__ float g_skip[NN * D];
__device__ float g_ssrc[NN * 16];
__device__ float g_stgt[NN * 16];
__device__ float g_c   [48];
__device__ __nv_bfloat16 g_Ahi[NN * D];
__device__ __nv_bfloat16 g_Alo[NN * D];
__device__ __nv_bfloat16 g_Bhi[5 * D * D];
__device__ __nv_bfloat16 g_Blo[5 * D * D];
// CSR
__device__ int   g_cnt[NN];
__device__ int   g_rowptr[NN + 1];
__device__ int   g_pos[NN];
__device__ int   g_partial[NN];
__device__ int   g_bsum[64];
__device__ int2  g_epack[NE];

// ---------------- helpers ----------------------------------------------------
__device__ __forceinline__ uint32_t smem_u32(const void* p) {
    uint32_t a;
    asm("{ .reg .u64 t; cvta.to.shared.u64 t, %1; cvt.u32.u64 %0, t; }" : "=r"(a) : "l"(p));
    return a;
}
__device__ __forceinline__ void ldmx4(uint32_t& r0, uint32_t& r1, uint32_t& r2, uint32_t& r3,
                                      uint32_t addr) {
    asm volatile("ldmatrix.sync.aligned.m8n8.x4.shared.b16 {%0,%1,%2,%3}, [%4];"
                 : "=r"(r0), "=r"(r1), "=r"(r2), "=r"(r3) : "r"(addr));
}
__device__ __forceinline__ void mma_bf16(float* d, const uint32_t* a, const uint32_t* b) {
    asm volatile(
        "mma.sync.aligned.m16n8k16.row.col.f32.bf16.bf16.f32 "
        "{%0,%1,%2,%3}, {%4,%5,%6,%7}, {%8,%9}, {%0,%1,%2,%3};"
        : "+f"(d[0]), "+f"(d[1]), "+f"(d[2]), "+f"(d[3])
        : "r"(a[0]), "r"(a[1]), "r"(a[2]), "r"(a[3]), "r"(b[0]), "r"(b[1]));
}
__device__ __forceinline__ void cp_async16(uint32_t sdst, const void* gsrc) {
    asm volatile("cp.async.cg.shared.global [%0], [%1], 16;" :: "r"(sdst), "l"(gsrc) : "memory");
}
__device__ __forceinline__ void cp_commit() {
    asm volatile("cp.async.commit_group;" ::: "memory");
}
template <int N>
__device__ __forceinline__ void cp_wait() {
    asm volatile("cp.async.wait_group %0;" :: "n"(N) : "memory");
}
#define SWZ64(x) ((x) ^ (((x) >> 3) & 0x30))

// ---------------- fp32 -> split-bf16 conversion ------------------------------
__global__ void convA_kernel(const float* __restrict__ X, __nv_bfloat16* __restrict__ Ahi,
                             __nv_bfloat16* __restrict__ Alo, int total2) {
    int i = blockIdx.x * blockDim.x + threadIdx.x;
    if (i >= total2) return;
    float2 v = ((const float2*)X)[i];
    __nv_bfloat16 h0 = __float2bfloat16(v.x);
    __nv_bfloat16 h1 = __float2bfloat16(v.y);
    ((__nv_bfloat162*)Ahi)[i] = __halves2bfloat162(h0, h1);
    __nv_bfloat16 l0 = __float2bfloat16(v.x - __bfloat162float(h0));
    __nv_bfloat16 l1 = __float2bfloat16(v.y - __bfloat162float(h1));
    ((__nv_bfloat162*)Alo)[i] = __halves2bfloat162(l0, l1);
}

// all 5 weight sets in one launch.
__global__ void convB_all_kernel(const float* __restrict__ W0, const float* __restrict__ Ws0,
                                 const float* __restrict__ W1, const float* __restrict__ Ws1,
                                 const float* __restrict__ W2,
                                 __nv_bfloat16* __restrict__ Bhi, __nv_bfloat16* __restrict__ Blo) {
    int idx = blockIdx.x * blockDim.x + threadIdx.x;
    const int S128 = 256 * 128;
    const int S256 = 256 * 256;
    const float* W;
    int K, slot, loc;
    if (idx < 2 * S128) {
        slot = idx / S128; loc = idx % S128; K = 128;
        W = slot ? Ws0 : W0;
    } else {
        int r = idx - 2 * S128;
        if (r >= 3 * S256) return;
        slot = 2 + r / S256; loc = r % S256; K = 256;
        W = (slot == 2) ? W1 : (slot == 3) ? Ws1 : W2;
    }
    int k = loc / 256, n = loc & 255;
    float v = W[k * 256 + n];
    __nv_bfloat16 h = __float2bfloat16(v);
    size_t off = (size_t)slot * D * D + (size_t)n * K + k;
    Bhi[off] = h;
    Blo[off] = __float2bfloat16(v - __bfloat162float(h));
}

// ---------------- zero the score accumulators --------------------------------
__global__ void zero_scores_kernel(float* __restrict__ ssrc, float* __restrict__ stgt, int total) {
    int i = blockIdx.x * blockDim.x + threadIdx.x;
    if (i < total) { ssrc[i] = 0.f; stgt[i] = 0.f; }
}

// ---------------- cp.async double-buffered mma.sync GEMM --------------------
// blockIdx.z==0: proj weights -> fp16 H + fused attention scores (atomicAdd).
// blockIdx.z==1: skip weights -> fp32 Cskip.
// 2 CTAs/SM for cross-CTA pipeline overlap (single change vs R12).
#define ST_AHI 0
#define ST_ALO 8192
#define ST_BHI 16384
#define ST_BLO 24576
#define ST_STRIDE 32768
#define GEMM_SMEM 65536

__global__ __launch_bounds__(256, 2) void gemm_mma_kernel(
    const __nv_bfloat16* __restrict__ Ahi, const __nv_bfloat16* __restrict__ Alo,
    const __nv_bfloat16* __restrict__ Bhi0, const __nv_bfloat16* __restrict__ Blo0,
    float* __restrict__ Cskip, __half* __restrict__ H,
    const float* __restrict__ avs, const float* __restrict__ avt,
    float* __restrict__ ssrc, float* __restrict__ stgt,
    int M, int K, int nh) {
    extern __shared__ char smem[];
    int tid = threadIdx.x, wid = tid >> 5, lane = tid & 31;
    int m0 = blockIdx.y * 128, n0 = blockIdx.x * 128;
    int z = blockIdx.z;
    int wm = wid >> 2, wn = wid & 3;
    const __nv_bfloat16* Bhi = Bhi0 + (size_t)z * D * D;
    const __nv_bfloat16* Blo = Blo0 + (size_t)z * D * D;

    uint32_t sb = smem_u32(smem);
    float acc[4][4][4];
#pragma unroll
    for (int i = 0; i < 4; i++)
#pragma unroll
        for (int j = 0; j < 4; j++)
#pragma unroll
            for (int q = 0; q < 4; q++) acc[i][j][q] = 0.f;

    int iters = K >> 5;
    auto issue_load = [&](int c) {
        uint32_t st = sb + (c & 1) * ST_STRIDE;
#pragma unroll
        for (int it = 0; it < 2; it++) {
            int i = tid + it * 256;
            int row = i >> 2, c16 = i & 3;
            uint32_t soff = SWZ64(row * 64 + c16 * 16);
            int gm = m0 + row;
            if (gm >= M) gm = M - 1;
            size_t go = (size_t)gm * K + c * 32 + c16 * 8;
            cp_async16(st + ST_AHI + soff, Ahi + go);
            cp_async16(st + ST_ALO + soff, Alo + go);
            size_t gb = (size_t)(n0 + row) * K + c * 32 + c16 * 8;
            cp_async16(st + ST_BHI + soff, Bhi + gb);
            cp_async16(st + ST_BLO + soff, Blo + gb);
        }
        cp_commit();
    };
    issue_load(0);
    for (int c = 0; c < iters; c++) {
        if (c + 1 < iters) { issue_load(c + 1); cp_wait<1>(); }
        else cp_wait<0>();
        __syncthreads();
        uint32_t st = sb + (c & 1) * ST_STRIDE;
        uint32_t sA0 = st + ST_AHI, sA1 = st + ST_ALO;
        uint32_t sB0 = st + ST_BHI, sB1 = st + ST_BLO;
#pragma unroll
        for (int ks = 0; ks < 2; ks++) {
            uint32_t ah[4][4], al[4][4], bh[4][2], bl[4][2];
#pragma unroll
            for (int mf = 0; mf < 4; mf++) {
                int row = wm * 64 + mf * 16 + (lane & 15);
                uint32_t off = SWZ64(row * 64 + ks * 32 + (lane >> 4) * 16);
                ldmx4(ah[mf][0], ah[mf][1], ah[mf][2], ah[mf][3], sA0 + off);
                ldmx4(al[mf][0], al[mf][1], al[mf][2], al[mf][3], sA1 + off);
            }
#pragma unroll
            for (int nf2 = 0; nf2 < 2; nf2++) {
                int row = wn * 32 + nf2 * 16 + (lane & 15);
                uint32_t off = SWZ64(row * 64 + ks * 32 + (lane >> 4) * 16);
                uint32_t t0, t1, t2, t3;
                ldmx4(t0, t1, t2, t3, sB0 + off);
                bh[nf2 * 2][0] = t0; bh[nf2 * 2][1] = t2;
                bh[nf2 * 2 + 1][0] = t1; bh[nf2 * 2 + 1][1] = t3;
                ldmx4(t0, t1, t2, t3, sB1 + off);
                bl[nf2 * 2][0] = t0; bl[nf2 * 2][1] = t2;
                bl[nf2 * 2 + 1][0] = t1; bl[nf2 * 2 + 1][1] = t3;
            }
#pragma unroll
            for (int mf = 0; mf < 4; mf++)
#pragma unroll
                for (int nf = 0; nf < 4; nf++) {
                    mma_bf16(acc[mf][nf], ah[mf], bh[nf]);
                    mma_bf16(acc[mf][nf], ah[mf], bl[nf]);
                    mma_bf16(acc[mf][nf], al[mf], bh[nf]);
                }
        }
        __syncthreads();
    }

    if (z == 0) {
        // ---- writeback fp16 proj + fused attention scores ----
        int colbase = n0 + wn * 32 + (lane & 3) * 2;
#pragma unroll
        for (int mf = 0; mf < 4; mf++) {
            int r0 = m0 + wm * 64 + mf * 16 + (lane >> 2);
#pragma unroll
            for (int nf = 0; nf < 4; nf++) {
                int col = colbase + nf * 8;
                if (r0 < M)
                    *(__half2*)(H + (size_t)r0 * 256 + col) =
                        __float22half2_rn(make_float2(acc[mf][nf][0], acc[mf][nf][1]));
                if (r0 + 8 < M)
                    *(__half2*)(H + (size_t)(r0 + 8) * 256 + col) =
                        __float22half2_rn(make_float2(acc[mf][nf][2], acc[mf][nf][3]));
            }
            // fused scores: partials per (head-half, row)
            float ps[2][2] = {{0.f, 0.f}, {0.f, 0.f}};
            float pt[2][2] = {{0.f, 0.f}, {0.f, 0.f}};
#pragma unroll
            for (int nf = 0; nf < 4; nf++) {
                int col = colbase + nf * 8;
                float2 a1 = *(const float2*)(avs + col);
                float2 a2 = *(const float2*)(avt + col);
                int hh = (nh == 16) ? (nf >> 1) : 0;
                ps[hh][0] += acc[mf][nf][0] * a1.x + acc[mf][nf][1] * a1.y;
                ps[hh][1] += acc[mf][nf][2] * a1.x + acc[mf][nf][3] * a1.y;
                pt[hh][0] += acc[mf][nf][0] * a2.x + acc[mf][nf][1] * a2.y;
                pt[hh][1] += acc[mf][nf][2] * a2.x + acc[mf][nf][3] * a2.y;
            }
#pragma unroll
            for (int o = 1; o < 4; o <<= 1) {
#pragma unroll
                for (int hh = 0; hh < 2; hh++)
#pragma unroll
                    for (int rr = 0; rr < 2; rr++) {
                        ps[hh][rr] += __shfl_xor_sync(0xffffffffu, ps[hh][rr], o);
                        pt[hh][rr] += __shfl_xor_sync(0xffffffffu, pt[hh][rr], o);
                    }
            }
            if ((lane & 3) == 0) {
                if (nh == 16) {
                    int h0 = (n0 + wn * 32) >> 4;
                    if (r0 < M) {
                        atomicAdd(&ssrc[r0 * 16 + h0], ps[0][0]);
                        atomicAdd(&ssrc[r0 * 16 + h0 + 1], ps[1][0]);
                        atomicAdd(&stgt[r0 * 16 + h0], pt[0][0]);
                        atomicAdd(&stgt[r0 * 16 + h0 + 1], pt[1][0]);
                    }
                    if (r0 + 8 < M) {
                        atomicAdd(&ssrc[(r0 + 8) * 16 + h0], ps[0][1]);
                        atomicAdd(&ssrc[(r0 + 8) * 16 + h0 + 1], ps[1][1]);
                        atomicAdd(&stgt[(r0 + 8) * 16 + h0], pt[0][1]);
                        atomicAdd(&stgt[(r0 + 8) * 16 + h0 + 1], pt[1][1]);
                    }
                } else {
                    if (r0 < M) {
                        atomicAdd(&ssrc[r0], ps[0][0] + ps[1][0]);
                        atomicAdd(&stgt[r0], pt[0][0] + pt[1][0]);
                    }
                    if (r0 + 8 < M) {
                        atomicAdd(&ssrc[r0 + 8], ps[0][1] + ps[1][1]);
                        atomicAdd(&stgt[r0 + 8], pt[0][1] + pt[1][1]);
                    }
                }
            }
        }
    } else {
        // ---- writeback fp32 skip ----
#pragma unroll
        for (int mf = 0; mf < 4; mf++) {
            int r0 = m0 + wm * 64 + mf * 16 + (lane >> 2);
#pragma unroll
            for (int nf = 0; nf < 4; nf++) {
                int col = n0 + wn * 32 + nf * 8 + (lane & 3) * 2;
                if (r0 < M)
                    *(float2*)(Cskip + (size_t)r0 * 256 + col) =
                        make_float2(acc[mf][nf][0], acc[mf][nf][1]);
                if (r0 + 8 < M)
                    *(float2*)(Cskip + (size_t)(r0 + 8) * 256 + col) =
                        make_float2(acc[mf][nf][2], acc[mf][nf][3]);
            }
        }
    }
}

// ---------------- CSR build --------------------------------------------------
__global__ void csr_zero_kernel(int* __restrict__ cnt) {
    int i = blockIdx.x * blockDim.x + threadIdx.x;
    if (i < NN) cnt[i] = 0;
}
__global__ void csr_count_kernel(const int* __restrict__ tgt, int* __restrict__ cnt) {
    int e = blockIdx.x * blockDim.x + threadIdx.x;
    if (e < NE) atomicAdd(&cnt[tgt[e]], 1);
}
// multi-block scan, phase 1: per-block inclusive scan + block sums
__global__ void csr_scan1_kernel(const int* __restrict__ cnt, int* __restrict__ partial,
                                 int* __restrict__ bsum) {
    __shared__ int sh[1024];
    int b = blockIdx.x, tid = threadIdx.x;
    int i = b * 1024 + tid;
    int v = (i < NN) ? cnt[i] : 0;
    sh[tid] = v;
    __syncthreads();
    for (int off = 1; off < 1024; off <<= 1) {
        int t = (tid >= off) ? sh[tid - off] : 0;
        __syncthreads();
        sh[tid] += t;
        __syncthreads();
    }
    if (i < NN) partial[i] = sh[tid];
    if (tid == 1023) bsum[b] = sh[1023];
}
// phase 2: exclusive scan of block sums (NB <= 64, single tiny block)
__global__ void csr_scan2_kernel(int* __restrict__ bsum) {
    if (threadIdx.x == 0) {
        int run = 0;
        for (int j = 0; j < NB; j++) {
            int t = bsum[j];
            bsum[j] = run;
            run += t;
        }
    }
}
// phase 3: apply offsets -> rowptr, pos
__global__ void csr_scan3_kernel(const int* __restrict__ cnt, const int* __restrict__ partial,
                                 const int* __restrict__ bsum,
                                 int* __restrict__ rowptr, int* __restrict__ pos) {
    int i = blockIdx.x * blockDim.x + threadIdx.x;
    if (i >= NN) return;
    int inc = partial[i] + bsum[i >> 10];
    rowptr[i + 1] = inc;
    pos[i] = inc - cnt[i];
    if (i == 0) rowptr[0] = 0;
}
__global__ void csr_scatter_kernel(const int* __restrict__ src, const int* __restrict__ tgt,
                                   const float* __restrict__ prob, int* __restrict__ pos,
                                   int2* __restrict__ epack) {
    int e = blockIdx.x * blockDim.x + threadIdx.x;
    if (e >= NE) return;
    int i = atomicAdd(&pos[tgt[e]], 1);
    epack[i] = make_int2(src[e], __float_as_int(prob[e]));
}

// ---------------- tp constants for all 3 layers in one launch ---------------
__global__ void tp_const_all_kernel(const float* __restrict__ Wtp0, const float* __restrict__ a0,
                                    const float* __restrict__ Wtp1, const float* __restrict__ a1,
                                    const float* __restrict__ Wtp2, const float* __restrict__ a2,
                                    float* __restrict__ c) {
    __shared__ float tmp[D];
    int L = blockIdx.x;
    int j = threadIdx.x;
    const float* W = (L == 0) ? Wtp0 : (L == 1) ? Wtp1 : Wtp2;
    const float* A = (L == 0) ? a0 : (L == 1) ? a1 : a2;
    tmp[j] = W[j] * A[j];
    __syncthreads();
    if (L < 2) {
        if (j < 16) {
            float s = 0.f;
            for (int f = 0; f < 16; f++) s += tmp[j * 16 + f];
            c[L * 16 + j] = s;
        }
    } else {
        if (j == 0) {
            float s = 0.f;
            for (int f = 0; f < 256; f++) s += tmp[f];
            c[32] = s;
        }
    }
}

// ---------------- fused node aggregation + epilogue -------------------------
// warp per target node; 4-wide edge unroll (locked config).
template <int NH, bool LN, bool WBF, bool WOUT>
__global__ __launch_bounds__(256) void node_aggr_kernel(
    const int* __restrict__ rowptr, const int2* __restrict__ epack,
    const float* __restrict__ ssrc, const float* __restrict__ stgt,
    const float* __restrict__ c,
    const __half* __restrict__ projh, const float* __restrict__ skip,
    const float* __restrict__ bias,
    const float* __restrict__ lng, const float* __restrict__ lnb,
    float* __restrict__ out, __nv_bfloat16* __restrict__ ohi,
    __nv_bfloat16* __restrict__ olo) {
    int n = (blockIdx.x * blockDim.x + threadIdx.x) >> 5;
    int lane = threadIdx.x & 31;
    if (n >= NN) return;

    float stg = 0.f, cc = 0.f;
    if (lane < NH) {
        stg = stgt[n * NH + lane];
        cc  = c[lane];
    }
    int beg = rowptr[n], end = rowptr[n + 1];
    int myhead = (NH == 16) ? (lane >> 1) : 0;

    float acc[8];
#pragma unroll
    for (int q = 0; q < 8; q++) acc[q] = 0.f;
    float den = 0.f;

    int i = beg;
    for (; i + 4 <= end; i += 4) {
        int2 e0 = epack[i], e1 = epack[i + 1], e2 = epack[i + 2], e3 = epack[i + 3];
        uint4 pv0 = ((const uint4*)(projh + (size_t)e0.x * D))[lane];
        uint4 pv1 = ((const uint4*)(projh + (size_t)e1.x * D))[lane];
        uint4 pv2 = ((const uint4*)(projh + (size_t)e2.x * D))[lane];
        uint4 pv3 = ((const uint4*)(projh + (size_t)e3.x * D))[lane];
        float w0 = 0.f, w1 = 0.f, w2 = 0.f, w3 = 0.f;
        if (lane < NH) {
            float v0 = ssrc[e0.x * NH + lane] + stg + __int_as_float(e0.y) * cc;
            float v1 = ssrc[e1.x * NH + lane] + stg + __int_as_float(e1.y) * cc;
            float v2 = ssrc[e2.x * NH + lane] + stg + __int_as_float(e2.y) * cc;
            float v3 = ssrc[e3.x * NH + lane] + stg + __int_as_float(e3.y) * cc;
            v0 = v0 > 0.f ? v0 : 0.2f * v0;
            v1 = v1 > 0.f ? v1 : 0.2f * v1;
            v2 = v2 > 0.f ? v2 : 0.2f * v2;
            v3 = v3 > 0.f ? v3 : 0.2f * v3;
            w0 = __expf(v0); w1 = __expf(v1); w2 = __expf(v2); w3 = __expf(v3);
            den += (w0 + w1) + (w2 + w3);
        }
        float wj0 = __shfl_sync(0xffffffffu, w0, myhead);
        float wj1 = __shfl_sync(0xffffffffu, w1, myhead);
        float wj2 = __shfl_sync(0xffffffffu, w2, myhead);
        float wj3 = __shfl_sync(0xffffffffu, w3, myhead);
        const __half2* h0 = (const __half2*)&pv0;
        const __half2* h1 = (const __half2*)&pv1;
        const __half2* h2 = (const __half2*)&pv2;
        const __half2* h3 = (const __half2*)&pv3;
#pragma unroll
        for (int q = 0; q < 4; q++) {
            float2 f0 = __half22float2(h0[q]);
            float2 f1 = __half22float2(h1[q]);
            float2 f2 = __half22float2(h2[q]);
            float2 f3 = __half22float2(h3[q]);
            acc[q * 2 + 0] += (wj0 * f0.x + wj1 * f1.x) + (wj2 * f2.x + wj3 * f3.x);
            acc[q * 2 + 1] += (wj0 * f0.y + wj1 * f1.y) + (wj2 * f2.y + wj3 * f3.y);
        }
    }
    for (; i < end; i++) {
        int2 e0 = epack[i];
        uint4 pv0 = ((const uint4*)(projh + (size_t)e0.x * D))[lane];
        float w0 = 0.f;
        if (lane < NH) {
            float v0 = ssrc[e0.x * NH + lane] + stg + __int_as_float(e0.y) * cc;
            v0 = v0 > 0.f ? v0 : 0.2f * v0;
            w0 = __expf(v0);
            den += w0;
        }
        float wj0 = __shfl_sync(0xffffffffu, w0, myhead);
        const __half2* h0 = (const __half2*)&pv0;
#pragma unroll
        for (int q = 0; q < 4; q++) {
            float2 f0 = __half22float2(h0[q]);
            acc[q * 2 + 0] += wj0 * f0.x;
            acc[q * 2 + 1] += wj0 * f0.y;
        }
    }

    // epilogue: cols 8*lane + 0..7
    float vals[8];
    size_t base = (size_t)n * D;
    float dh = __shfl_sync(0xffffffffu, den, myhead) + 1e-16f;
    float rdh = 1.f / dh;
#pragma unroll
    for (int k = 0; k < 2; k++) {
        float4 sk = ((const float4*)(skip + base))[lane * 2 + k];
        float4 bi = ((const float4*)bias)[lane * 2 + k];
        float4 r;
        r.x = acc[k * 4 + 0] * rdh + sk.x + bi.x;
        r.y = acc[k * 4 + 1] * rdh + sk.y + bi.y;
        r.z = acc[k * 4 + 2] * rdh + sk.z + bi.z;
        r.w = acc[k * 4 + 3] * rdh + sk.w + bi.w;
        vals[k * 4 + 0] = r.x > 0.f ? r.x : (__expf(r.x) - 1.f);
        vals[k * 4 + 1] = r.y > 0.f ? r.y : (__expf(r.y) - 1.f);
        vals[k * 4 + 2] = r.z > 0.f ? r.z : (__expf(r.z) - 1.f);
        vals[k * 4 + 3] = r.w > 0.f ? r.w : (__expf(r.w) - 1.f);
    }
    if (LN) {
        float s = 0.f;
#pragma unroll
        for (int q = 0; q < 8; q++) s += vals[q];
#pragma unroll
        for (int o = 16; o > 0; o >>= 1) s += __shfl_xor_sync(0xffffffffu, s, o);
        float mean = s * (1.f / 256.f);
        float v2 = 0.f;
#pragma unroll
        for (int q = 0; q < 8; q++) {
            vals[q] -= mean;
            v2 += vals[q] * vals[q];
        }
#pragma unroll
        for (int o = 16; o > 0; o >>= 1) v2 += __shfl_xor_sync(0xffffffffu, v2, o);
        float rstd = rsqrtf(v2 * (1.f / 256.f) + 1e-5f);
#pragma unroll
        for (int k = 0; k < 2; k++) {
            float4 gg = ((const float4*)lng)[lane * 2 + k];
            float4 bb = ((const float4*)lnb)[lane * 2 + k];
            vals[k * 4 + 0] = vals[k * 4 + 0] * rstd * gg.x + bb.x;
            vals[k * 4 + 1] = vals[k * 4 + 1] * rstd * gg.y + bb.y;
            vals[k * 4 + 2] = vals[k * 4 + 2] * rstd * gg.z + bb.z;
            vals[k * 4 + 3] = vals[k * 4 + 3] * rstd * gg.w + bb.w;
        }
    }
#pragma unroll
    for (int k = 0; k < 2; k++) {
        float4 r = make_float4(vals[k * 4], vals[k * 4 + 1], vals[k * 4 + 2], vals[k * 4 + 3]);
        if (WOUT) ((float4*)(out + base))[lane * 2 + k] = r;
        if (WBF) {
            __nv_bfloat16 h0 = __float2bfloat16(r.x);
            __nv_bfloat16 h1 = __float2bfloat16(r.y);
            __nv_bfloat16 h2 = __float2bfloat16(r.z);
            __nv_bfloat16 h3 = __float2bfloat16(r.w);
            ((__nv_bfloat162*)(ohi + base))[lane * 4 + k * 2]     = __halves2bfloat162(h0, h1);
            ((__nv_bfloat162*)(ohi + base))[lane * 4 + k * 2 + 1] = __halves2bfloat162(h2, h3);
            ((__nv_bfloat162*)(olo + base))[lane * 4 + k * 2] = __halves2bfloat162(
                __float2bfloat16(r.x - __bfloat162float(h0)),
                __float2bfloat16(r.y - __bfloat162float(h1)));
            ((__nv_bfloat162*)(olo + base))[lane * 4 + k * 2 + 1] = __halves2bfloat162(
                __float2bfloat16(r.z - __bfloat162float(h2)),
                __float2bfloat16(r.w - __bfloat162float(h3)));
        }
    }
}

// ---------------- final gather ----------------------------------------------
__global__ void gather_kernel(const float* __restrict__ h, const int* __restrict__ x,
                              float4* __restrict__ out, int total4) {
    int idx = blockIdx.x * blockDim.x + threadIdx.x;
    if (idx >= total4) return;
    int i = idx / (D / 4), j = idx % (D / 4);
    out[idx] = ((const float4*)(h + (size_t)x[i] * D))[j];
}

// ---------------- host orchestration ----------------------------------------
static float* symaddr(const void* sym) {
    void* p = nullptr;
    cudaGetSymbolAddress(&p, sym);
    return (float*)p;
}
static __nv_bfloat16* symaddr_bf(const void* sym) {
    void* p = nullptr;
    cudaGetSymbolAddress(&p, sym);
    return (__nv_bfloat16*)p;
}
static __half* symaddr_h(const void* sym) {
    void* p = nullptr;
    cudaGetSymbolAddress(&p, sym);
    return (__half*)p;
}
static int* symaddr_i(const void* sym) {
    void* p = nullptr;
    cudaGetSymbolAddress(&p, sym);
    return (int*)p;
}

extern "C" void kernel_launch(void* const* d_in, const int* in_sizes, int n_in,
                              void* d_out, int out_size) {
    const float* nf   = (const float*)d_in[0];
    const int*   ei   = (const int*)  d_in[1];
    const float* prob = (const float*)d_in[2];
    const int*   x    = (const int*)  d_in[3];
    const float* W0     = (const float*)d_in[4];
    const float* a_src0 = (const float*)d_in[5];
    const float* a_tgt0 = (const float*)d_in[6];
    const float* Wtp0   = (const float*)d_in[7];
    const float* a_tp0  = (const float*)d_in[8];
    const float* Wskip0 = (const float*)d_in[9];
    const float* b0     = (const float*)d_in[10];
    const float* W1     = (const float*)d_in[11];
    const float* a_src1 = (const float*)d_in[12];
    const float* a_tgt1 = (const float*)d_in[13];
    const float* Wtp1   = (const float*)d_in[14];
    const float* a_tp1  = (const float*)d_in[15];
    const float* Wskip1 = (const float*)d_in[16];
    const float* b1     = (const float*)d_in[17];
    const float* ln1_g  = (const float*)d_in[18];
    const float* ln1_b  = (const float*)d_in[19];
    const float* W2     = (const float*)d_in[20];
    const float* a_src2 = (const float*)d_in[21];
    const float* a_tgt2 = (const float*)d_in[22];
    const float* Wtp2   = (const float*)d_in[23];
    const float* a_tp2  = (const float*)d_in[24];
    const float* b2     = (const float*)d_in[25];
    const float* ln2_g  = (const float*)d_in[26];
    const float* ln2_b  = (const float*)d_in[27];

    static cudaStream_t sCsr = nullptr;
    static cudaEvent_t evFork = nullptr, evJoin = nullptr;
    if (!sCsr) {
        cudaFuncSetAttribute(gemm_mma_kernel, cudaFuncAttributeMaxDynamicSharedMemorySize, GEMM_SMEM);
        cudaStreamCreateWithFlags(&sCsr, cudaStreamNonBlocking);
        cudaEventCreateWithFlags(&evFork, cudaEventDisableTiming);
        cudaEventCreateWithFlags(&evJoin, cudaEventDisableTiming);
    }

    const int* src = ei;
    const int* tgt = ei + NE;
    float* bufA = symaddr(g_bufA);
    float* bufB = symaddr(g_bufB);
    __half* projh = symaddr_h(g_projh);
    float* skip = symaddr(g_skip);
    float* ssrc = symaddr(g_ssrc);
    float* stgt = symaddr(g_stgt);
    float* cbuf = symaddr(g_c);
    __nv_bfloat16* Ahi = symaddr_bf(g_Ahi);
    __nv_bfloat16* Alo = symaddr_bf(g_Alo);
    __nv_bfloat16* Bhi = symaddr_bf(g_Bhi);
    __nv_bfloat16* Blo = symaddr_bf(g_Blo);
    int* cnt     = symaddr_i(g_cnt);
    int* rowptr  = symaddr_i(g_rowptr);
    int* pos     = symaddr_i(g_pos);
    int* partial = symaddr_i(g_partial);
    int* bsum    = symaddr_i(g_bsum);
    int2* epack  = (int2*)symaddr_i(g_epack);

    const size_t WS = (size_t)D * D;

    // ---- fork: CSR build on side stream (fast multi-block scan) ----
    cudaEventRecord(evFork, 0);
    cudaStreamWaitEvent(sCsr, evFork, 0);
    csr_zero_kernel<<<(NN + 255) / 256, 256, 0, sCsr>>>(cnt);
    csr_count_kernel<<<(NE + 255) / 256, 256, 0, sCsr>>>(tgt, cnt);
    csr_scan1_kernel<<<NB, 1024, 0, sCsr>>>(cnt, partial, bsum);
    csr_scan2_kernel<<<1, 32, 0, sCsr>>>(bsum);
    csr_scan3_kernel<<<(NN + 255) / 256, 256, 0, sCsr>>>(cnt, partial, bsum, rowptr, pos);
    csr_scatter_kernel<<<(NE + 255) / 256, 256, 0, sCsr>>>(src, tgt, prob, pos, epack);
    cudaEventRecord(evJoin, sCsr);

    // ---- main stream: conversions ----
    const int CONVB_TOTAL = 2 * 256 * 128 + 3 * 256 * 256;
    convB_all_kernel<<<(CONVB_TOTAL + 255) / 256, 256>>>(W0, Wskip0, W1, Wskip1, W2, Bhi, Blo);
    tp_const_all_kernel<<<3, 256>>>(Wtp0, a_tp0, Wtp1, a_tp1, Wtp2, a_tp2, cbuf);
    convA_kernel<<<(NN * 128 / 2 + 255) / 256, 256>>>(nf, Ahi, Alo, NN * 128 / 2);

    int aggGrid = (NN * 32 + 255) / 256;
    dim3 ggrid2(2, (NN + 127) / 128, 2);
    dim3 ggrid1(2, (NN + 127) / 128, 1);
    int zsGrid = (NN * 16 + 255) / 256;

    // ---- layer 0: 128 -> 256, 16 heads, no LN ----
    zero_scores_kernel<<<zsGrid, 256>>>(ssrc, stgt, NN * 16);
    gemm_mma_kernel<<<ggrid2, 256, GEMM_SMEM>>>(Ahi, Alo, Bhi, Blo, skip, projh,
                                                a_src0, a_tgt0, ssrc, stgt, NN, 128, 16);
    cudaStreamWaitEvent(0, evJoin, 0);
    node_aggr_kernel<16, false, true, false><<<aggGrid, 256>>>(
        rowptr, epack, ssrc, stgt, cbuf, projh, skip, b0,
        nullptr, nullptr, nullptr, Ahi, Alo);

    // ---- layer 1: 256 -> 256, 16 heads, LN ----
    zero_scores_kernel<<<zsGrid, 256>>>(ssrc, stgt, NN * 16);
    gemm_mma_kernel<<<ggrid2, 256, GEMM_SMEM>>>(Ahi, Alo, Bhi + 2 * WS, Blo + 2 * WS, skip, projh,
                                                a_src1, a_tgt1, ssrc, stgt, NN, 256, 16);
    node_aggr_kernel<16, true, true, true><<<aggGrid, 256>>>(
        rowptr, epack, ssrc, stgt, cbuf + 16, projh, skip, b1,
        ln1_g, ln1_b, bufB, Ahi, Alo);

    // ---- layer 2: 256 -> 256, 1 head, identity skip, LN ----
    zero_scores_kernel<<<(NN + 255) / 256, 256>>>(ssrc, stgt, NN);
    gemm_mma_kernel<<<ggrid1, 256, GEMM_SMEM>>>(Ahi, Alo, Bhi + 4 * WS, Blo + 4 * WS, nullptr, projh,
                                                a_src2, a_tgt2, ssrc, stgt, NN, 256, 1);
    node_aggr_kernel<1, true, false, true><<<aggGrid, 256>>>(
        rowptr, epack, ssrc, stgt, cbuf + 32, projh, bufB, b2,
        ln2_g, ln2_b, bufA, nullptr, nullptr);

    gather_kernel<<<(out_size / 4 + 255) / 256, 256>>>(bufA, x, (float4*)d_out, out_size / 4);
}

// round 16
// speedup vs baseline: 1.1672x; 1.0051x over previous
#include <cuda_runtime.h>
#include <cuda_bf16.h>
#include <cuda_fp16.h>
#include <cstdint>

#define NN 50000
#define NE 800000
#define D  256
#define NB ((NN + 1023) / 1024)

// ---------------- scratch (static device memory, no allocs) ----------------
__device__ float g_bufA[NN * D];
__device__ float g_bufB[NN * D];
__device__ __half g_projh[NN * D];
__device__ float g_skip[NN * D];
__device__ float g_ssrc[3][NN * 16];
__device__ float g_stgt[3][NN * 16];
__device__ float g_c   [48];
__device__ __nv_bfloat16 g_Ahi[NN * D];
__device__ __nv_bfloat16 g_Alo[NN * D];
__device__ __nv_bfloat16 g_Bhi[5 * D * D];
__device__ __nv_bfloat16 g_Blo[5 * D * D];
// CSR
__device__ int   g_cnt[NN];
__device__ int   g_rowptr[NN + 1];
__device__ int   g_pos[NN];
__device__ int   g_partial[NN];
__device__ int   g_bsum[64];
__device__ int2  g_epack[NE];

// ---------------- helpers ----------------------------------------------------
__device__ __forceinline__ uint32_t smem_u32(const void* p) {
    uint32_t a;
    asm("{ .reg .u64 t; cvta.to.shared.u64 t, %1; cvt.u32.u64 %0, t; }" : "=r"(a) : "l"(p));
    return a;
}
__device__ __forceinline__ void ldmx4(uint32_t& r0, uint32_t& r1, uint32_t& r2, uint32_t& r3,
                                      uint32_t addr) {
    asm volatile("ldmatrix.sync.aligned.m8n8.x4.shared.b16 {%0,%1,%2,%3}, [%4];"
                 : "=r"(r0), "=r"(r1), "=r"(r2), "=r"(r3) : "r"(addr));
}
__device__ __forceinline__ void mma_bf16(float* d, const uint32_t* a, const uint32_t* b) {
    asm volatile(
        "mma.sync.aligned.m16n8k16.row.col.f32.bf16.bf16.f32 "
        "{%0,%1,%2,%3}, {%4,%5,%6,%7}, {%8,%9}, {%0,%1,%2,%3};"
        : "+f"(d[0]), "+f"(d[1]), "+f"(d[2]), "+f"(d[3])
        : "r"(a[0]), "r"(a[1]), "r"(a[2]), "r"(a[3]), "r"(b[0]), "r"(b[1]));
}
__device__ __forceinline__ void cp_async16(uint32_t sdst, const void* gsrc) {
    asm volatile("cp.async.cg.shared.global [%0], [%1], 16;" :: "r"(sdst), "l"(gsrc) : "memory");
}
__device__ __forceinline__ void cp_commit() {
    asm volatile("cp.async.commit_group;" ::: "memory");
}
template <int N>
__device__ __forceinline__ void cp_wait() {
    asm volatile("cp.async.wait_group %0;" :: "n"(N) : "memory");
}
#define SWZ64(x) ((x) ^ (((x) >> 3) & 0x30))

// ---------------- fp32 -> split-bf16 conversion ------------------------------
__global__ void convA_kernel(const float* __restrict__ X, __nv_bfloat16* __restrict__ Ahi,
                             __nv_bfloat16* __restrict__ Alo, int total2) {
    int i = blockIdx.x * blockDim.x + threadIdx.x;
    if (i >= total2) return;
    float2 v = ((const float2*)X)[i];
    __nv_bfloat16 h0 = __float2bfloat16(v.x);
    __nv_bfloat16 h1 = __float2bfloat16(v.y);
    ((__nv_bfloat162*)Ahi)[i] = __halves2bfloat162(h0, h1);
    __nv_bfloat16 l0 = __float2bfloat16(v.x - __bfloat162float(h0));
    __nv_bfloat16 l1 = __float2bfloat16(v.y - __bfloat162float(h1));
    ((__nv_bfloat162*)Alo)[i] = __halves2bfloat162(l0, l1);
}

// all 5 weight sets in one launch.
__global__ void convB_all_kernel(const float* __restrict__ W0, const float* __restrict__ Ws0,
                                 const float* __restrict__ W1, const float* __restrict__ Ws1,
                                 const float* __restrict__ W2,
                                 __nv_bfloat16* __restrict__ Bhi, __nv_bfloat16* __restrict__ Blo) {
    int idx = blockIdx.x * blockDim.x + threadIdx.x;
    const int S128 = 256 * 128;
    const int S256 = 256 * 256;
    const float* W;
    int K, slot, loc;
    if (idx < 2 * S128) {
        slot = idx / S128; loc = idx % S128; K = 128;
        W = slot ? Ws0 : W0;
    } else {
        int r = idx - 2 * S128;
        if (r >= 3 * S256) return;
        slot = 2 + r / S256; loc = r % S256; K = 256;
        W = (slot == 2) ? W1 : (slot == 3) ? Ws1 : W2;
    }
    int k = loc / 256, n = loc & 255;
    float v = W[k * 256 + n];
    __nv_bfloat16 h = __float2bfloat16(v);
    size_t off = (size_t)slot * D * D + (size_t)n * K + k;
    Bhi[off] = h;
    Blo[off] = __float2bfloat16(v - __bfloat162float(h));
}

// ---------------- zero the score accumulators --------------------------------
__global__ void zero_scores_kernel(float* __restrict__ ssrc, float* __restrict__ stgt, int total) {
    int i = blockIdx.x * blockDim.x + threadIdx.x;
    if (i < total) { ssrc[i] = 0.f; stgt[i] = 0.f; }
}

// ---------------- cp.async double-buffered mma.sync GEMM --------------------
// blockIdx.z==0: proj weights -> fp16 H + fused attention scores (atomicAdd).
// blockIdx.z==1: skip weights -> fp32 Cskip.  2 CTAs/SM (R15 config).
#define ST_AHI 0
#define ST_ALO 8192
#define ST_BHI 16384
#define ST_BLO 24576
#define ST_STRIDE 32768
#define GEMM_SMEM 65536

__global__ __launch_bounds__(256, 2) void gemm_mma_kernel(
    const __nv_bfloat16* __restrict__ Ahi, const __nv_bfloat16* __restrict__ Alo,
    const __nv_bfloat16* __restrict__ Bhi0, const __nv_bfloat16* __restrict__ Blo0,
    float* __restrict__ Cskip, __half* __restrict__ H,
    const float* __restrict__ avs, const float* __restrict__ avt,
    float* __restrict__ ssrc, float* __restrict__ stgt,
    int M, int K, int nh) {
    extern __shared__ char smem[];
    int tid = threadIdx.x, wid = tid >> 5, lane = tid & 31;
    int m0 = blockIdx.y * 128, n0 = blockIdx.x * 128;
    int z = blockIdx.z;
    int wm = wid >> 2, wn = wid & 3;
    const __nv_bfloat16* Bhi = Bhi0 + (size_t)z * D * D;
    const __nv_bfloat16* Blo = Blo0 + (size_t)z * D * D;

    uint32_t sb = smem_u32(smem);
    float acc[4][4][4];
#pragma unroll
    for (int i = 0; i < 4; i++)
#pragma unroll
        for (int j = 0; j < 4; j++)
#pragma unroll
            for (int q = 0; q < 4; q++) acc[i][j][q] = 0.f;

    int iters = K >> 5;
    auto issue_load = [&](int c) {
        uint32_t st = sb + (c & 1) * ST_STRIDE;
#pragma unroll
        for (int it = 0; it < 2; it++) {
            int i = tid + it * 256;
            int row = i >> 2, c16 = i & 3;
            uint32_t soff = SWZ64(row * 64 + c16 * 16);
            int gm = m0 + row;
            if (gm >= M) gm = M - 1;
            size_t go = (size_t)gm * K + c * 32 + c16 * 8;
            cp_async16(st + ST_AHI + soff, Ahi + go);
            cp_async16(st + ST_ALO + soff, Alo + go);
            size_t gb = (size_t)(n0 + row) * K + c * 32 + c16 * 8;
            cp_async16(st + ST_BHI + soff, Bhi + gb);
            cp_async16(st + ST_BLO + soff, Blo + gb);
        }
        cp_commit();
    };
    issue_load(0);
    for (int c = 0; c < iters; c++) {
        if (c + 1 < iters) { issue_load(c + 1); cp_wait<1>(); }
        else cp_wait<0>();
        __syncthreads();
        uint32_t st = sb + (c & 1) * ST_STRIDE;
        uint32_t sA0 = st + ST_AHI, sA1 = st + ST_ALO;
        uint32_t sB0 = st + ST_BHI, sB1 = st + ST_BLO;
#pragma unroll
        for (int ks = 0; ks < 2; ks++) {
            uint32_t ah[4][4], al[4][4], bh[4][2], bl[4][2];
#pragma unroll
            for (int mf = 0; mf < 4; mf++) {
                int row = wm * 64 + mf * 16 + (lane & 15);
                uint32_t off = SWZ64(row * 64 + ks * 32 + (lane >> 4) * 16);
                ldmx4(ah[mf][0], ah[mf][1], ah[mf][2], ah[mf][3], sA0 + off);
                ldmx4(al[mf][0], al[mf][1], al[mf][2], al[mf][3], sA1 + off);
            }
#pragma unroll
            for (int nf2 = 0; nf2 < 2; nf2++) {
                int row = wn * 32 + nf2 * 16 + (lane & 15);
                uint32_t off = SWZ64(row * 64 + ks * 32 + (lane >> 4) * 16);
                uint32_t t0, t1, t2, t3;
                ldmx4(t0, t1, t2, t3, sB0 + off);
                bh[nf2 * 2][0] = t0; bh[nf2 * 2][1] = t2;
                bh[nf2 * 2 + 1][0] = t1; bh[nf2 * 2 + 1][1] = t3;
                ldmx4(t0, t1, t2, t3, sB1 + off);
                bl[nf2 * 2][0] = t0; bl[nf2 * 2][1] = t2;
                bl[nf2 * 2 + 1][0] = t1; bl[nf2 * 2 + 1][1] = t3;
            }
#pragma unroll
            for (int mf = 0; mf < 4; mf++)
#pragma unroll
                for (int nf = 0; nf < 4; nf++) {
                    mma_bf16(acc[mf][nf], ah[mf], bh[nf]);
                    mma_bf16(acc[mf][nf], ah[mf], bl[nf]);
                    mma_bf16(acc[mf][nf], al[mf], bh[nf]);
                }
        }
        __syncthreads();
    }

    if (z == 0) {
        // ---- writeback fp16 proj + fused attention scores ----
        int colbase = n0 + wn * 32 + (lane & 3) * 2;
#pragma unroll
        for (int mf = 0; mf < 4; mf++) {
            int r0 = m0 + wm * 64 + mf * 16 + (lane >> 2);
#pragma unroll
            for (int nf = 0; nf < 4; nf++) {
                int col = colbase + nf * 8;
                if (r0 < M)
                    *(__half2*)(H + (size_t)r0 * 256 + col) =
                        __float22half2_rn(make_float2(acc[mf][nf][0], acc[mf][nf][1]));
                if (r0 + 8 < M)
                    *(__half2*)(H + (size_t)(r0 + 8) * 256 + col) =
                        __float22half2_rn(make_float2(acc[mf][nf][2], acc[mf][nf][3]));
            }
            // fused scores: partials per (head-half, row)
            float ps[2][2] = {{0.f, 0.f}, {0.f, 0.f}};
            float pt[2][2] = {{0.f, 0.f}, {0.f, 0.f}};
#pragma unroll
            for (int nf = 0; nf < 4; nf++) {
                int col = colbase + nf * 8;
                float2 a1 = *(const float2*)(avs + col);
                float2 a2 = *(const float2*)(avt + col);
                int hh = (nh == 16) ? (nf >> 1) : 0;
                ps[hh][0] += acc[mf][nf][0] * a1.x + acc[mf][nf][1] * a1.y;
                ps[hh][1] += acc[mf][nf][2] * a1.x + acc[mf][nf][3] * a1.y;
                pt[hh][0] += acc[mf][nf][0] * a2.x + acc[mf][nf][1] * a2.y;
                pt[hh][1] += acc[mf][nf][2] * a2.x + acc[mf][nf][3] * a2.y;
            }
#pragma unroll
            for (int o = 1; o < 4; o <<= 1) {
#pragma unroll
                for (int hh = 0; hh < 2; hh++)
#pragma unroll
                    for (int rr = 0; rr < 2; rr++) {
                        ps[hh][rr] += __shfl_xor_sync(0xffffffffu, ps[hh][rr], o);
                        pt[hh][rr] += __shfl_xor_sync(0xffffffffu, pt[hh][rr], o);
                    }
            }
            if ((lane & 3) == 0) {
                if (nh == 16) {
                    int h0 = (n0 + wn * 32) >> 4;
                    if (r0 < M) {
                        atomicAdd(&ssrc[r0 * 16 + h0], ps[0][0]);
                        atomicAdd(&ssrc[r0 * 16 + h0 + 1], ps[1][0]);
                        atomicAdd(&stgt[r0 * 16 + h0], pt[0][0]);
                        atomicAdd(&stgt[r0 * 16 + h0 + 1], pt[1][0]);
                    }
                    if (r0 + 8 < M) {
                        atomicAdd(&ssrc[(r0 + 8) * 16 + h0], ps[0][1]);
                        atomicAdd(&ssrc[(r0 + 8) * 16 + h0 + 1], ps[1][1]);
                        atomicAdd(&stgt[(r0 + 8) * 16 + h0], pt[0][1]);
                        atomicAdd(&stgt[(r0 + 8) * 16 + h0 + 1], pt[1][1]);
                    }
                } else {
                    if (r0 < M) {
                        atomicAdd(&ssrc[r0], ps[0][0] + ps[1][0]);
                        atomicAdd(&stgt[r0], pt[0][0] + pt[1][0]);
                    }
                    if (r0 + 8 < M) {
                        atomicAdd(&ssrc[r0 + 8], ps[0][1] + ps[1][1]);
                        atomicAdd(&stgt[r0 + 8], pt[0][1] + pt[1][1]);
                    }
                }
            }
        }
    } else {
        // ---- writeback fp32 skip ----
#pragma unroll
        for (int mf = 0; mf < 4; mf++) {
            int r0 = m0 + wm * 64 + mf * 16 + (lane >> 2);
#pragma unroll
            for (int nf = 0; nf < 4; nf++) {
                int col = n0 + wn * 32 + nf * 8 + (lane & 3) * 2;
                if (r0 < M)
                    *(float2*)(Cskip + (size_t)r0 * 256 + col) =
                        make_float2(acc[mf][nf][0], acc[mf][nf][1]);
                if (r0 + 8 < M)
                    *(float2*)(Cskip + (size_t)(r0 + 8) * 256 + col) =
                        make_float2(acc[mf][nf][2], acc[mf][nf][3]);
            }
        }
    }
}

// ---------------- CSR build --------------------------------------------------
__global__ void csr_zero_kernel(int* __restrict__ cnt) {
    int i = blockIdx.x * blockDim.x + threadIdx.x;
    if (i < NN) cnt[i] = 0;
}
__global__ void csr_count_kernel(const int* __restrict__ tgt, int* __restrict__ cnt) {
    int e = blockIdx.x * blockDim.x + threadIdx.x;
    if (e < NE) atomicAdd(&cnt[tgt[e]], 1);
}
__global__ void csr_scan1_kernel(const int* __restrict__ cnt, int* __restrict__ partial,
                                 int* __restrict__ bsum) {
    __shared__ int sh[1024];
    int b = blockIdx.x, tid = threadIdx.x;
    int i = b * 1024 + tid;
    int v = (i < NN) ? cnt[i] : 0;
    sh[tid] = v;
    __syncthreads();
    for (int off = 1; off < 1024; off <<= 1) {
        int t = (tid >= off) ? sh[tid - off] : 0;
        __syncthreads();
        sh[tid] += t;
        __syncthreads();
    }
    if (i < NN) partial[i] = sh[tid];
    if (tid == 1023) bsum[b] = sh[1023];
}
__global__ void csr_scan2_kernel(int* __restrict__ bsum) {
    if (threadIdx.x == 0) {
        int run = 0;
        for (int j = 0; j < NB; j++) {
            int t = bsum[j];
            bsum[j] = run;
            run += t;
        }
    }
}
__global__ void csr_scan3_kernel(const int* __restrict__ cnt, const int* __restrict__ partial,
                                 const int* __restrict__ bsum,
                                 int* __restrict__ rowptr, int* __restrict__ pos) {
    int i = blockIdx.x * blockDim.x + threadIdx.x;
    if (i >= NN) return;
    int inc = partial[i] + bsum[i >> 10];
    rowptr[i + 1] = inc;
    pos[i] = inc - cnt[i];
    if (i == 0) rowptr[0] = 0;
}
__global__ void csr_scatter_kernel(const int* __restrict__ src, const int* __restrict__ tgt,
                                   const float* __restrict__ prob, int* __restrict__ pos,
                                   int2* __restrict__ epack) {
    int e = blockIdx.x * blockDim.x + threadIdx.x;
    if (e >= NE) return;
    int i = atomicAdd(&pos[tgt[e]], 1);
    epack[i] = make_int2(src[e], __float_as_int(prob[e]));
}

// ---------------- tp constants for all 3 layers in one launch ---------------
__global__ void tp_const_all_kernel(const float* __restrict__ Wtp0, const float* __restrict__ a0,
                                    const float* __restrict__ Wtp1, const float* __restrict__ a1,
                                    const float* __restrict__ Wtp2, const float* __restrict__ a2,
                                    float* __restrict__ c) {
    __shared__ float tmp[D];
    int L = blockIdx.x;
    int j = threadIdx.x;
    const float* W = (L == 0) ? Wtp0 : (L == 1) ? Wtp1 : Wtp2;
    const float* A = (L == 0) ? a0 : (L == 1) ? a1 : a2;
    tmp[j] = W[j] * A[j];
    __syncthreads();
    if (L < 2) {
        if (j < 16) {
            float s = 0.f;
            for (int f = 0; f < 16; f++) s += tmp[j * 16 + f];
            c[L * 16 + j] = s;
        }
    } else {
        if (j == 0) {
            float s = 0.f;
            for (int f = 0; f < 256; f++) s += tmp[f];
            c[32] = s;
        }
    }
}

// ---------------- fused node aggregation + epilogue -------------------------
// warp per target node; 4-wide edge unroll (locked config).
template <int NH, bool LN, bool WBF, bool WOUT>
__global__ __launch_bounds__(256) void node_aggr_kernel(
    const int* __restrict__ rowptr, const int2* __restrict__ epack,
    const float* __restrict__ ssrc, const float* __restrict__ stgt,
    const float* __restrict__ c,
    const __half* __restrict__ projh, const float* __restrict__ skip,
    const float* __restrict__ bias,
    const float* __restrict__ lng, const float* __restrict__ lnb,
    float* __restrict__ out, __nv_bfloat16* __restrict__ ohi,
    __nv_bfloat16* __restrict__ olo) {
    int n = (blockIdx.x * blockDim.x + threadIdx.x) >> 5;
    int lane = threadIdx.x & 31;
    if (n >= NN) return;

    float stg = 0.f, cc = 0.f;
    if (lane < NH) {
        stg = stgt[n * NH + lane];
        cc  = c[lane];
    }
    int beg = rowptr[n], end = rowptr[n + 1];
    int myhead = (NH == 16) ? (lane >> 1) : 0;

    float acc[8];
#pragma unroll
    for (int q = 0; q < 8; q++) acc[q] = 0.f;
    float den = 0.f;

    int i = beg;
    for (; i + 4 <= end; i += 4) {
        int2 e0 = epack[i], e1 = epack[i + 1], e2 = epack[i + 2], e3 = epack[i + 3];
        uint4 pv0 = ((const uint4*)(projh + (size_t)e0.x * D))[lane];
        uint4 pv1 = ((const uint4*)(projh + (size_t)e1.x * D))[lane];
        uint4 pv2 = ((const uint4*)(projh + (size_t)e2.x * D))[lane];
        uint4 pv3 = ((const uint4*)(projh + (size_t)e3.x * D))[lane];
        float w0 = 0.f, w1 = 0.f, w2 = 0.f, w3 = 0.f;
        if (lane < NH) {
            float v0 = ssrc[e0.x * NH + lane] + stg + __int_as_float(e0.y) * cc;
            float v1 = ssrc[e1.x * NH + lane] + stg + __int_as_float(e1.y) * cc;
            float v2 = ssrc[e2.x * NH + lane] + stg + __int_as_float(e2.y) * cc;
            float v3 = ssrc[e3.x * NH + lane] + stg + __int_as_float(e3.y) * cc;
            v0 = v0 > 0.f ? v0 : 0.2f * v0;
            v1 = v1 > 0.f ? v1 : 0.2f * v1;
            v2 = v2 > 0.f ? v2 : 0.2f * v2;
            v3 = v3 > 0.f ? v3 : 0.2f * v3;
            w0 = __expf(v0); w1 = __expf(v1); w2 = __expf(v2); w3 = __expf(v3);
            den += (w0 + w1) + (w2 + w3);
        }
        float wj0 = __shfl_sync(0xffffffffu, w0, myhead);
        float wj1 = __shfl_sync(0xffffffffu, w1, myhead);
        float wj2 = __shfl_sync(0xffffffffu, w2, myhead);
        float wj3 = __shfl_sync(0xffffffffu, w3, myhead);
        const __half2* h0 = (const __half2*)&pv0;
        const __half2* h1 = (const __half2*)&pv1;
        const __half2* h2 = (const __half2*)&pv2;
        const __half2* h3 = (const __half2*)&pv3;
#pragma unroll
        for (int q = 0; q < 4; q++) {
            float2 f0 = __half22float2(h0[q]);
            float2 f1 = __half22float2(h1[q]);
            float2 f2 = __half22float2(h2[q]);
            float2 f3 = __half22float2(h3[q]);
            acc[q * 2 + 0] += (wj0 * f0.x + wj1 * f1.x) + (wj2 * f2.x + wj3 * f3.x);
            acc[q * 2 + 1] += (wj0 * f0.y + wj1 * f1.y) + (wj2 * f2.y + wj3 * f3.y);
        }
    }
    for (; i < end; i++) {
        int2 e0 = epack[i];
        uint4 pv0 = ((const uint4*)(projh + (size_t)e0.x * D))[lane];
        float w0 = 0.f;
        if (lane < NH) {
            float v0 = ssrc[e0.x * NH + lane] + stg + __int_as_float(e0.y) * cc;
            v0 = v0 > 0.f ? v0 : 0.2f * v0;
            w0 = __expf(v0);
            den += w0;
        }
        float wj0 = __shfl_sync(0xffffffffu, w0, myhead);
        const __half2* h0 = (const __half2*)&pv0;
#pragma unroll
        for (int q = 0; q < 4; q++) {
            float2 f0 = __half22float2(h0[q]);
            acc[q * 2 + 0] += wj0 * f0.x;
            acc[q * 2 + 1] += wj0 * f0.y;
        }
    }

    // epilogue: cols 8*lane + 0..7
    float vals[8];
    size_t base = (size_t)n * D;
    float dh = __shfl_sync(0xffffffffu, den, myhead) + 1e-16f;
    float rdh = 1.f / dh;
#pragma unroll
    for (int k = 0; k < 2; k++) {
        float4 sk = ((const float4*)(skip + base))[lane * 2 + k];
        float4 bi = ((const float4*)bias)[lane * 2 + k];
        float4 r;
        r.x = acc[k * 4 + 0] * rdh + sk.x + bi.x;
        r.y = acc[k * 4 + 1] * rdh + sk.y + bi.y;
        r.z = acc[k * 4 + 2] * rdh + sk.z + bi.z;
        r.w = acc[k * 4 + 3] * rdh + sk.w + bi.w;
        vals[k * 4 + 0] = r.x > 0.f ? r.x : (__expf(r.x) - 1.f);
        vals[k * 4 + 1] = r.y > 0.f ? r.y : (__expf(r.y) - 1.f);
        vals[k * 4 + 2] = r.z > 0.f ? r.z : (__expf(r.z) - 1.f);
        vals[k * 4 + 3] = r.w > 0.f ? r.w : (__expf(r.w) - 1.f);
    }
    if (LN) {
        float s = 0.f;
#pragma unroll
        for (int q = 0; q < 8; q++) s += vals[q];
#pragma unroll
        for (int o = 16; o > 0; o >>= 1) s += __shfl_xor_sync(0xffffffffu, s, o);
        float mean = s * (1.f / 256.f);
        float v2 = 0.f;
#pragma unroll
        for (int q = 0; q < 8; q++) {
            vals[q] -= mean;
            v2 += vals[q] * vals[q];
        }
#pragma unroll
        for (int o = 16; o > 0; o >>= 1) v2 += __shfl_xor_sync(0xffffffffu, v2, o);
        float rstd = rsqrtf(v2 * (1.f / 256.f) + 1e-5f);
#pragma unroll
        for (int k = 0; k < 2; k++) {
            float4 gg = ((const float4*)lng)[lane * 2 + k];
            float4 bb = ((const float4*)lnb)[lane * 2 + k];
            vals[k * 4 + 0] = vals[k * 4 + 0] * rstd * gg.x + bb.x;
            vals[k * 4 + 1] = vals[k * 4 + 1] * rstd * gg.y + bb.y;
            vals[k * 4 + 2] = vals[k * 4 + 2] * rstd * gg.z + bb.z;
            vals[k * 4 + 3] = vals[k * 4 + 3] * rstd * gg.w + bb.w;
        }
    }
#pragma unroll
    for (int k = 0; k < 2; k++) {
        float4 r = make_float4(vals[k * 4], vals[k * 4 + 1], vals[k * 4 + 2], vals[k * 4 + 3]);
        if (WOUT) ((float4*)(out + base))[lane * 2 + k] = r;
        if (WBF) {
            __nv_bfloat16 h0 = __float2bfloat16(r.x);
            __nv_bfloat16 h1 = __float2bfloat16(r.y);
            __nv_bfloat16 h2 = __float2bfloat16(r.z);
            __nv_bfloat16 h3 = __float2bfloat16(r.w);
            ((__nv_bfloat162*)(ohi + base))[lane * 4 + k * 2]     = __halves2bfloat162(h0, h1);
            ((__nv_bfloat162*)(ohi + base))[lane * 4 + k * 2 + 1] = __halves2bfloat162(h2, h3);
            ((__nv_bfloat162*)(olo + base))[lane * 4 + k * 2] = __halves2bfloat162(
                __float2bfloat16(r.x - __bfloat162float(h0)),
                __float2bfloat16(r.y - __bfloat162float(h1)));
            ((__nv_bfloat162*)(olo + base))[lane * 4 + k * 2 + 1] = __halves2bfloat162(
                __float2bfloat16(r.z - __bfloat162float(h2)),
                __float2bfloat16(r.w - __bfloat162float(h3)));
        }
    }
}

// ---------------- final gather ----------------------------------------------
__global__ void gather_kernel(const float* __restrict__ h, const int* __restrict__ x,
                              float4* __restrict__ out, int total4) {
    int idx = blockIdx.x * blockDim.x + threadIdx.x;
    if (idx >= total4) return;
    int i = idx / (D / 4), j = idx % (D / 4);
    out[idx] = ((const float4*)(h + (size_t)x[i] * D))[j];
}

// ---------------- host orchestration ----------------------------------------
static float* symaddr(const void* sym) {
    void* p = nullptr;
    cudaGetSymbolAddress(&p, sym);
    return (float*)p;
}
static __nv_bfloat16* symaddr_bf(const void* sym) {
    void* p = nullptr;
    cudaGetSymbolAddress(&p, sym);
    return (__nv_bfloat16*)p;
}
static __half* symaddr_h(const void* sym) {
    void* p = nullptr;
    cudaGetSymbolAddress(&p, sym);
    return (__half*)p;
}
static int* symaddr_i(const void* sym) {
    void* p = nullptr;
    cudaGetSymbolAddress(&p, sym);
    return (int*)p;
}

extern "C" void kernel_launch(void* const* d_in, const int* in_sizes, int n_in,
                              void* d_out, int out_size) {
    const float* nf   = (const float*)d_in[0];
    const int*   ei   = (const int*)  d_in[1];
    const float* prob = (const float*)d_in[2];
    const int*   x    = (const int*)  d_in[3];
    const float* W0     = (const float*)d_in[4];
    const float* a_src0 = (const float*)d_in[5];
    const float* a_tgt0 = (const float*)d_in[6];
    const float* Wtp0   = (const float*)d_in[7];
    const float* a_tp0  = (const float*)d_in[8];
    const float* Wskip0 = (const float*)d_in[9];
    const float* b0     = (const float*)d_in[10];
    const float* W1     = (const float*)d_in[11];
    const float* a_src1 = (const float*)d_in[12];
    const float* a_tgt1 = (const float*)d_in[13];
    const float* Wtp1   = (const float*)d_in[14];
    const float* a_tp1  = (const float*)d_in[15];
    const float* Wskip1 = (const float*)d_in[16];
    const float* b1     = (const float*)d_in[17];
    const float* ln1_g  = (const float*)d_in[18];
    const float* ln1_b  = (const float*)d_in[19];
    const float* W2     = (const float*)d_in[20];
    const float* a_src2 = (const float*)d_in[21];
    const float* a_tgt2 = (const float*)d_in[22];
    const float* Wtp2   = (const float*)d_in[23];
    const float* a_tp2  = (const float*)d_in[24];
    const float* b2     = (const float*)d_in[25];
    const float* ln2_g  = (const float*)d_in[26];
    const float* ln2_b  = (const float*)d_in[27];

    static cudaStream_t sCsr = nullptr;
    static cudaEvent_t evFork = nullptr, evJoin = nullptr, evW = nullptr;
    if (!sCsr) {
        cudaFuncSetAttribute(gemm_mma_kernel, cudaFuncAttributeMaxDynamicSharedMemorySize, GEMM_SMEM);
        cudaStreamCreateWithFlags(&sCsr, cudaStreamNonBlocking);
        cudaEventCreateWithFlags(&evFork, cudaEventDisableTiming);
        cudaEventCreateWithFlags(&evJoin, cudaEventDisableTiming);
        cudaEventCreateWithFlags(&evW, cudaEventDisableTiming);
    }

    const int* src = ei;
    const int* tgt = ei + NE;
    float* bufA = symaddr(g_bufA);
    float* bufB = symaddr(g_bufB);
    __half* projh = symaddr_h(g_projh);
    float* skip = symaddr(g_skip);
    float* ssrc = symaddr(g_ssrc);   // 3 stacked layers of NN*16
    float* stgt = symaddr(g_stgt);
    float* cbuf = symaddr(g_c);
    __nv_bfloat16* Ahi = symaddr_bf(g_Ahi);
    __nv_bfloat16* Alo = symaddr_bf(g_Alo);
    __nv_bfloat16* Bhi = symaddr_bf(g_Bhi);
    __nv_bfloat16* Blo = symaddr_bf(g_Blo);
    int* cnt     = symaddr_i(g_cnt);
    int* rowptr  = symaddr_i(g_rowptr);
    int* pos     = symaddr_i(g_pos);
    int* partial = symaddr_i(g_partial);
    int* bsum    = symaddr_i(g_bsum);
    int2* epack  = (int2*)symaddr_i(g_epack);

    const size_t WS = (size_t)D * D;
    const int SB = NN * 16;  // per-layer score buffer stride

    // ---- fork: zero all score buffers then CSR build on side stream ----
    cudaEventRecord(evFork, 0);
    cudaStreamWaitEvent(sCsr, evFork, 0);
    zero_scores_kernel<<<(3 * SB + 255) / 256, 256, 0, sCsr>>>(ssrc, stgt, 3 * SB);
    cudaEventRecord(evW, sCsr);   // score buffers zeroed
    csr_zero_kernel<<<(NN + 255) / 256, 256, 0, sCsr>>>(cnt);
    csr_count_kernel<<<(NE + 255) / 256, 256, 0, sCsr>>>(tgt, cnt);
    csr_scan1_kernel<<<NB, 1024, 0, sCsr>>>(cnt, partial, bsum);
    csr_scan2_kernel<<<1, 32, 0, sCsr>>>(bsum);
    csr_scan3_kernel<<<(NN + 255) / 256, 256, 0, sCsr>>>(cnt, partial, bsum, rowptr, pos);
    csr_scatter_kernel<<<(NE + 255) / 256, 256, 0, sCsr>>>(src, tgt, prob, pos, epack);
    cudaEventRecord(evJoin, sCsr);

    // ---- main stream: conversions (unchanged) ----
    const int CONVB_TOTAL = 2 * 256 * 128 + 3 * 256 * 256;
    convB_all_kernel<<<(CONVB_TOTAL + 255) / 256, 256>>>(W0, Wskip0, W1, Wskip1, W2, Bhi, Blo);
    tp_const_all_kernel<<<3, 256>>>(Wtp0, a_tp0, Wtp1, a_tp1, Wtp2, a_tp2, cbuf);
    convA_kernel<<<(NN * 128 / 2 + 255) / 256, 256>>>(nf, Ahi, Alo, NN * 128 / 2);
    cudaStreamWaitEvent(0, evW, 0);   // scores zeroed before first GEMM atomics

    int aggGrid = (NN * 32 + 255) / 256;
    dim3 ggrid2(2, (NN + 127) / 128, 2);
    dim3 ggrid1(2, (NN + 127) / 128, 1);

    // ---- layer 0: 128 -> 256, 16 heads, no LN ----
    gemm_mma_kernel<<<ggrid2, 256, GEMM_SMEM>>>(Ahi, Alo, Bhi, Blo, skip, projh,
                                                a_src0, a_tgt0, ssrc, stgt, NN, 128, 16);
    cudaStreamWaitEvent(0, evJoin, 0);
    node_aggr_kernel<16, false, true, false><<<aggGrid, 256>>>(
        rowptr, epack, ssrc, stgt, cbuf, projh, skip, b0,
        nullptr, nullptr, nullptr, Ahi, Alo);

    // ---- layer 1: 256 -> 256, 16 heads, LN ----
    gemm_mma_kernel<<<ggrid2, 256, GEMM_SMEM>>>(Ahi, Alo, Bhi + 2 * WS, Blo + 2 * WS, skip, projh,
                                                a_src1, a_tgt1, ssrc + SB, stgt + SB, NN, 256, 16);
    node_aggr_kernel<16, true, true, true><<<aggGrid, 256>>>(
        rowptr, epack, ssrc + SB, stgt + SB, cbuf + 16, projh, skip, b1,
        ln1_g, ln1_b, bufB, Ahi, Alo);

    // ---- layer 2: 256 -> 256, 1 head, identity skip, LN ----
    gemm_mma_kernel<<<ggrid1, 256, GEMM_SMEM>>>(Ahi, Alo, Bhi + 4 * WS, Blo + 4 * WS, nullptr, projh,
                                                a_src2, a_tgt2, ssrc + 2 * SB, stgt + 2 * SB, NN, 256, 1);
    node_aggr_kernel<1, true, false, true><<<aggGrid, 256>>>(
        rowptr, epack, ssrc + 2 * SB, stgt + 2 * SB, cbuf + 32, projh, bufB, b2,
        ln2_g, ln2_b, bufA, nullptr, nullptr);

    gather_kernel<<<(out_size / 4 + 255) / 256, 256>>>(bufA, x, (float4*)d_out, out_size / 4);
}